// round 1
// baseline (speedup 1.0000x reference)
#include <cuda_runtime.h>
#include <cuda_bf16.h>

#define NN 8192          // nodes
#define NE 262144        // edges
#define IND 128          // in dim
#define HID 256          // hidden

// ---------------- scratch (static device memory; no allocs allowed) ----------
__device__ int   g_is64;
__device__ int   g_src[NE];
__device__ int   g_dst[NE];
__device__ int   g_csr[NE];
__device__ int   g_rowstart[NN + 8];
__device__ int   g_degi[NN];
__device__ int   g_cursor[NN];
__device__ float g_rdeg[NN];
__device__ float g_mean1[NN * IND];     // 4 MB
__device__ float g_h1[NN * HID];        // 8 MB
__device__ float g_mean2[NN * HID];     // 8 MB
__device__ float g_h2[NN * HID];        // 8 MB
__device__ float g_li[NN];
__device__ float g_lj[NN];
__device__ float g_vl[HID];
__device__ float g_vr[HID];
__device__ float g_cc[2];

// ---------------- small utility kernels --------------------------------------

__global__ void init_zero_kernel() {
    int i = blockIdx.x * blockDim.x + threadIdx.x;
    if (i < NN) { g_degi[i] = 0; g_cursor[i] = 0; }
}

// Decide whether edge_index buffer is int64 or int32.
// If int64 (little-endian), hi words (odd int32 positions) of the first 2048
// values are all 0 (indices in [0, 8192)). If int32, they are random indices,
// virtually certainly not all zero.
__global__ void probe_kernel(const int* __restrict__ e) {
    __shared__ int any_nonzero;
    if (threadIdx.x == 0) any_nonzero = 0;
    __syncthreads();
    for (int i = threadIdx.x; i < 2048; i += blockDim.x) {
        if (e[2 * i + 1] != 0) any_nonzero = 1;
    }
    __syncthreads();
    if (threadIdx.x == 0) g_is64 = any_nonzero ? 0 : 1;
}

__global__ void convert_kernel(const int* __restrict__ e, int n_edges) {
    int i = blockIdx.x * blockDim.x + threadIdx.x;
    if (i >= n_edges) return;
    int s, d;
    if (g_is64) {
        s = e[2 * i];
        d = e[2 * (n_edges + i)];
    } else {
        s = e[i];
        d = e[n_edges + i];
    }
    g_src[i] = s;
    g_dst[i] = d;
    atomicAdd(&g_degi[d], 1);
}

// Exclusive prefix sum over g_degi (8192 entries) in a single 1024-thread block.
__global__ void scan_kernel() {
    __shared__ int ts[1024];
    int t = threadIdx.x;
    int base = t * 8;
    int loc[8];
    int s = 0;
#pragma unroll
    for (int j = 0; j < 8; j++) { loc[j] = s; s += g_degi[base + j]; }
    ts[t] = s;
    __syncthreads();
    for (int off = 1; off < 1024; off <<= 1) {
        int v = (t >= off) ? ts[t - off] : 0;
        __syncthreads();
        ts[t] += v;
        __syncthreads();
    }
    int excl = ts[t] - s;
#pragma unroll
    for (int j = 0; j < 8; j++) {
        g_rowstart[base + j] = excl + loc[j];
        int d = g_degi[base + j];
        g_rdeg[base + j] = 1.0f / (float)max(d, 1);
    }
    if (t == 1023) g_rowstart[NN] = excl + s;
}

__global__ void fill_kernel(int n_edges) {
    int i = blockIdx.x * blockDim.x + threadIdx.x;
    if (i >= n_edges) return;
    int d = g_dst[i];
    int p = atomicAdd(&g_cursor[d], 1);
    g_csr[g_rowstart[d] + p] = g_src[i];
}

// ---------------- aggregation (warp per node, gather over CSR) ---------------

__global__ void agg128_kernel(const float* __restrict__ x, float* __restrict__ out) {
    int w = (blockIdx.x * blockDim.x + threadIdx.x) >> 5;
    if (w >= NN) return;
    int lane = threadIdx.x & 31;
    int beg = g_rowstart[w], end = g_rowstart[w + 1];
    float4 acc = make_float4(0.f, 0.f, 0.f, 0.f);
    int j = beg;
    for (; j + 4 <= end; j += 4) {
        int s0 = g_csr[j], s1 = g_csr[j + 1], s2 = g_csr[j + 2], s3 = g_csr[j + 3];
        float4 v0 = *(const float4*)&x[s0 * IND + lane * 4];
        float4 v1 = *(const float4*)&x[s1 * IND + lane * 4];
        float4 v2 = *(const float4*)&x[s2 * IND + lane * 4];
        float4 v3 = *(const float4*)&x[s3 * IND + lane * 4];
        acc.x += v0.x + v1.x + v2.x + v3.x;
        acc.y += v0.y + v1.y + v2.y + v3.y;
        acc.z += v0.z + v1.z + v2.z + v3.z;
        acc.w += v0.w + v1.w + v2.w + v3.w;
    }
    for (; j < end; j++) {
        int s0 = g_csr[j];
        float4 v0 = *(const float4*)&x[s0 * IND + lane * 4];
        acc.x += v0.x; acc.y += v0.y; acc.z += v0.z; acc.w += v0.w;
    }
    float r = g_rdeg[w];
    acc.x *= r; acc.y *= r; acc.z *= r; acc.w *= r;
    *(float4*)&out[w * IND + lane * 4] = acc;
}

__global__ void agg256_kernel(const float* __restrict__ x, float* __restrict__ out) {
    int w = (blockIdx.x * blockDim.x + threadIdx.x) >> 5;
    if (w >= NN) return;
    int lane = threadIdx.x & 31;
    int beg = g_rowstart[w], end = g_rowstart[w + 1];
    float4 accA = make_float4(0.f, 0.f, 0.f, 0.f);
    float4 accB = make_float4(0.f, 0.f, 0.f, 0.f);
    int j = beg;
    for (; j + 2 <= end; j += 2) {
        int s0 = g_csr[j], s1 = g_csr[j + 1];
        float4 a0 = *(const float4*)&x[s0 * HID + lane * 4];
        float4 b0 = *(const float4*)&x[s0 * HID + 128 + lane * 4];
        float4 a1 = *(const float4*)&x[s1 * HID + lane * 4];
        float4 b1 = *(const float4*)&x[s1 * HID + 128 + lane * 4];
        accA.x += a0.x + a1.x; accA.y += a0.y + a1.y;
        accA.z += a0.z + a1.z; accA.w += a0.w + a1.w;
        accB.x += b0.x + b1.x; accB.y += b0.y + b1.y;
        accB.z += b0.z + b1.z; accB.w += b0.w + b1.w;
    }
    for (; j < end; j++) {
        int s0 = g_csr[j];
        float4 a0 = *(const float4*)&x[s0 * HID + lane * 4];
        float4 b0 = *(const float4*)&x[s0 * HID + 128 + lane * 4];
        accA.x += a0.x; accA.y += a0.y; accA.z += a0.z; accA.w += a0.w;
        accB.x += b0.x; accB.y += b0.y; accB.z += b0.z; accB.w += b0.w;
    }
    float r = g_rdeg[w];
    accA.x *= r; accA.y *= r; accA.z *= r; accA.w *= r;
    accB.x *= r; accB.y *= r; accB.z *= r; accB.w *= r;
    *(float4*)&out[w * HID + lane * 4] = accA;
    *(float4*)&out[w * HID + 128 + lane * 4] = accB;
}

// ---------------- dual-operand GEMM: C = relu(A1@W1.T + A2@W2.T + bias) ------
// A: [M, K] row-major; W: [256, K] row-major; C: [M, 256] row-major.
// Block tile 128x64, 128 threads, 8x8 microtile, BK=16.

template <int K, bool RELU>
__global__ __launch_bounds__(128) void gemm2_kernel(
    const float* __restrict__ A1, const float* __restrict__ W1,
    const float* __restrict__ A2, const float* __restrict__ W2,
    const float* __restrict__ bias, float* __restrict__ C) {
    const int BM = 128, BN = 64, BK = 16;
    __shared__ float As[BK][BM + 4];   // [16][132]
    __shared__ float Ws[BK][BN + 4];   // [16][68]
    int t = threadIdx.x;
    int rowBase = blockIdx.x * BM;
    int colBase = blockIdx.y * BN;
    int tr = (t / 8) * 8;   // 0..120
    int tc = (t % 8) * 8;   // 0..56
    float acc[8][8];
#pragma unroll
    for (int i = 0; i < 8; i++)
#pragma unroll
        for (int j = 0; j < 8; j++) acc[i][j] = 0.f;

    for (int pass = 0; pass < 2; pass++) {
        const float* A = pass ? A2 : A1;
        const float* W = pass ? W2 : W1;
        for (int k0 = 0; k0 < K; k0 += BK) {
            // load A tile (128x16) as 512 float4 by 128 threads
#pragma unroll
            for (int i = 0; i < 4; i++) {
                int r = (t / 4) + i * 32;
                int kc = (t % 4) * 4;
                float4 v = *(const float4*)&A[(size_t)(rowBase + r) * K + k0 + kc];
                As[kc + 0][r] = v.x; As[kc + 1][r] = v.y;
                As[kc + 2][r] = v.z; As[kc + 3][r] = v.w;
            }
            // load W tile (64x16) as 256 float4 by 128 threads
#pragma unroll
            for (int i = 0; i < 2; i++) {
                int r = (t / 4) + i * 32;
                int kc = (t % 4) * 4;
                float4 v = *(const float4*)&W[(size_t)(colBase + r) * K + k0 + kc];
                Ws[kc + 0][r] = v.x; Ws[kc + 1][r] = v.y;
                Ws[kc + 2][r] = v.z; Ws[kc + 3][r] = v.w;
            }
            __syncthreads();
#pragma unroll
            for (int kk = 0; kk < BK; kk++) {
                float4 a0 = *(const float4*)&As[kk][tr];
                float4 a1 = *(const float4*)&As[kk][tr + 4];
                float4 b0 = *(const float4*)&Ws[kk][tc];
                float4 b1 = *(const float4*)&Ws[kk][tc + 4];
                float a[8] = {a0.x, a0.y, a0.z, a0.w, a1.x, a1.y, a1.z, a1.w};
                float b[8] = {b0.x, b0.y, b0.z, b0.w, b1.x, b1.y, b1.z, b1.w};
#pragma unroll
                for (int i = 0; i < 8; i++)
#pragma unroll
                    for (int j = 0; j < 8; j++) acc[i][j] += a[i] * b[j];
            }
            __syncthreads();
        }
    }
    // epilogue
#pragma unroll
    for (int i = 0; i < 8; i++) {
        int row = rowBase + tr + i;
#pragma unroll
        for (int j = 0; j < 8; j += 4) {
            int col = colBase + tc + j;
            float4 o;
            o.x = acc[i][j + 0] + bias[col + 0];
            o.y = acc[i][j + 1] + bias[col + 1];
            o.z = acc[i][j + 2] + bias[col + 2];
            o.w = acc[i][j + 3] + bias[col + 3];
            if (RELU) {
                o.x = fmaxf(o.x, 0.f); o.y = fmaxf(o.y, 0.f);
                o.z = fmaxf(o.z, 0.f); o.w = fmaxf(o.w, 0.f);
            }
            *(float4*)&C[(size_t)row * HID + col] = o;
        }
    }
}

// ---------------- final-layer algebra ----------------------------------------
// li = h2 @ (w_out.T @ w_left) + b_out.w_left ; same for lj with w_right.

__global__ void vprep_kernel(const float* __restrict__ w_out,
                             const float* __restrict__ b_out,
                             const float* __restrict__ w_edge) {
    int k = threadIdx.x;  // 256 threads
    float sl = 0.f, sr = 0.f;
    for (int o = 0; o < HID; o++) {
        float w = w_out[o * HID + k];
        sl += w * w_edge[o];
        sr += w * w_edge[HID + o];
    }
    g_vl[k] = sl;
    g_vr[k] = sr;
    if (k == 0) {
        float cl = 0.f, cr = 0.f;
        for (int o = 0; o < HID; o++) {
            cl += b_out[o] * w_edge[o];
            cr += b_out[o] * w_edge[HID + o];
        }
        g_cc[0] = cl;
        g_cc[1] = cr;
    }
}

__global__ void lilj_kernel(const float* __restrict__ h) {
    int w = (blockIdx.x * blockDim.x + threadIdx.x) >> 5;
    if (w >= NN) return;
    int lane = threadIdx.x & 31;
    int k = lane * 8;
    float4 p0 = *(const float4*)&h[(size_t)w * HID + k];
    float4 p1 = *(const float4*)&h[(size_t)w * HID + k + 4];
    float4 vl0 = *(const float4*)&g_vl[k];
    float4 vl1 = *(const float4*)&g_vl[k + 4];
    float4 vr0 = *(const float4*)&g_vr[k];
    float4 vr1 = *(const float4*)&g_vr[k + 4];
    float sl = p0.x * vl0.x + p0.y * vl0.y + p0.z * vl0.z + p0.w * vl0.w +
               p1.x * vl1.x + p1.y * vl1.y + p1.z * vl1.z + p1.w * vl1.w;
    float sr = p0.x * vr0.x + p0.y * vr0.y + p0.z * vr0.z + p0.w * vr0.w +
               p1.x * vr1.x + p1.y * vr1.y + p1.z * vr1.z + p1.w * vr1.w;
#pragma unroll
    for (int off = 16; off > 0; off >>= 1) {
        sl += __shfl_xor_sync(0xFFFFFFFFu, sl, off);
        sr += __shfl_xor_sync(0xFFFFFFFFu, sr, off);
    }
    if (lane == 0) {
        g_li[w] = sl + g_cc[0];
        g_lj[w] = sr + g_cc[1];
    }
}

// ---------------- rank-1 broadcast output ------------------------------------
// out[i,j] = li[i] + lj[j] + b_edge[0]; tile 16 rows x 2048 cols per block.

__global__ __launch_bounds__(256) void out_kernel(float* __restrict__ out,
                                                  const float* __restrict__ b_edge) {
    __shared__ float slj[2048];
    __shared__ float sli[16];
    int colBase = blockIdx.x * 2048;
    int rowBase = blockIdx.y * 16;
    float be = b_edge[0];
    for (int c = threadIdx.x; c < 2048; c += 256) slj[c] = g_lj[colBase + c];
    if (threadIdx.x < 16) sli[threadIdx.x] = g_li[rowBase + threadIdx.x];
    __syncthreads();
#pragma unroll 4
    for (int r = 0; r < 16; r++) {
        float liv = sli[r] + be;
        size_t base = (size_t)(rowBase + r) * NN + colBase;
        for (int c = threadIdx.x; c < 512; c += 256) {
            float4 v = *(const float4*)&slj[c * 4];
            float4 o = make_float4(liv + v.x, liv + v.y, liv + v.z, liv + v.w);
            *(float4*)&out[base + c * 4] = o;
        }
    }
}

// ---------------- launcher ----------------------------------------------------

extern "C" void kernel_launch(void* const* d_in, const int* in_sizes, int n_in,
                              void* d_out, int out_size) {
    const float* x      = (const float*)d_in[0];
    const int*   edges  = (const int*)d_in[1];   // probed: int64 or int32
    const float* wl1    = (const float*)d_in[2];
    const float* bl1    = (const float*)d_in[3];
    const float* wr1    = (const float*)d_in[4];
    const float* wl2    = (const float*)d_in[5];
    const float* bl2    = (const float*)d_in[6];
    const float* wr2    = (const float*)d_in[7];
    const float* w_out  = (const float*)d_in[8];
    const float* b_out  = (const float*)d_in[9];
    const float* w_edge = (const float*)d_in[10];
    const float* b_edge = (const float*)d_in[11];
    float* out = (float*)d_out;

    int n_edges = NE;

    float* mean1 = nullptr; float* h1 = nullptr; float* mean2 = nullptr; float* h2 = nullptr;
    cudaGetSymbolAddress((void**)&mean1, g_mean1);
    cudaGetSymbolAddress((void**)&h1, g_h1);
    cudaGetSymbolAddress((void**)&mean2, g_mean2);
    cudaGetSymbolAddress((void**)&h2, g_h2);

    // graph build
    init_zero_kernel<<<(NN + 255) / 256, 256>>>();
    probe_kernel<<<1, 256>>>(edges);
    convert_kernel<<<(n_edges + 255) / 256, 256>>>(edges, n_edges);
    scan_kernel<<<1, 1024>>>();
    fill_kernel<<<(n_edges + 255) / 256, 256>>>(n_edges);

    // layer 1
    agg128_kernel<<<NN * 32 / 256, 256>>>(x, mean1);
    {
        dim3 grid(NN / 128, HID / 64);
        gemm2_kernel<IND, true><<<grid, 128>>>(mean1, wl1, x, wr1, bl1, h1);
    }
    // layer 2
    agg256_kernel<<<NN * 32 / 256, 256>>>(h1, mean2);
    {
        dim3 grid(NN / 128, HID / 64);
        gemm2_kernel<HID, true><<<grid, 128>>>(mean2, wl2, h1, wr2, bl2, h2);
    }
    // output head
    vprep_kernel<<<1, 256>>>(w_out, b_out, w_edge);
    lilj_kernel<<<NN * 32 / 256, 256>>>(h2);
    {
        dim3 grid(NN / 2048, NN / 16);
        out_kernel<<<grid, 256>>>(out, b_edge);
    }
}

// round 2
// speedup vs baseline: 1.3747x; 1.3747x over previous
#include <cuda_runtime.h>
#include <cuda_bf16.h>

#define NN 8192          // nodes
#define NE 262144        // edges
#define IND 128          // in dim
#define HID 256          // hidden

// ---------------- scratch (static device memory; no allocs allowed) ----------
__device__ int   g_is64;
__device__ int   g_src[NE];
__device__ int   g_dst[NE];
__device__ int   g_csr[NE];
__device__ int   g_rowstart[NN + 8];
__device__ int   g_degi[NN];
__device__ int   g_cursor[NN];
__device__ float g_rdeg[NN];
__device__ float g_mean1[NN * IND];     // 4 MB
__device__ float g_h1[NN * HID];        // 8 MB
__device__ float g_mean2[NN * HID];     // 8 MB
__device__ float g_h2[NN * HID];        // 8 MB
__device__ float g_li[NN];
__device__ float g_lj[NN];
__device__ float g_vl[HID];
__device__ float g_vr[HID];
__device__ float g_cc[2];

// ---------------- build chain ------------------------------------------------

// blocks 0..31 zero degi/cursor; block 32 probes int64 vs int32 layout.
__global__ void initprobe_kernel(const int* __restrict__ e) {
    if (blockIdx.x == 32) {
        __shared__ int any_nonzero;
        if (threadIdx.x == 0) any_nonzero = 0;
        __syncthreads();
        for (int i = threadIdx.x; i < 2048; i += blockDim.x) {
            if (e[2 * i + 1] != 0) any_nonzero = 1;
        }
        __syncthreads();
        if (threadIdx.x == 0) g_is64 = any_nonzero ? 0 : 1;
        return;
    }
    int i = blockIdx.x * blockDim.x + threadIdx.x;
    g_degi[i] = 0;
    g_cursor[i] = 0;
}

__global__ void convert_kernel(const int* __restrict__ e, int n_edges) {
    int i = blockIdx.x * blockDim.x + threadIdx.x;
    if (i >= n_edges) return;
    int s, d;
    if (g_is64) {
        s = e[2 * i];
        d = e[2 * (n_edges + i)];
    } else {
        s = e[i];
        d = e[n_edges + i];
    }
    g_src[i] = s;
    g_dst[i] = d;
    atomicAdd(&g_degi[d], 1);
}

// Exclusive prefix sum over g_degi (8192 entries), shuffle-based, 2 syncs.
__global__ void scan_kernel() {
    int t = threadIdx.x;           // 1024 threads
    int lane = t & 31, w = t >> 5;
    int base = t * 8;
    int loc[8];
    int s = 0;
#pragma unroll
    for (int j = 0; j < 8; j++) { loc[j] = s; s += g_degi[base + j]; }
    // warp inclusive scan of s
    int v = s;
#pragma unroll
    for (int off = 1; off < 32; off <<= 1) {
        int u = __shfl_up_sync(0xFFFFFFFFu, v, off);
        if (lane >= off) v += u;
    }
    __shared__ int wt[32];
    if (lane == 31) wt[w] = v;
    __syncthreads();
    if (w == 0) {
        int x = wt[lane];
#pragma unroll
        for (int off = 1; off < 32; off <<= 1) {
            int u = __shfl_up_sync(0xFFFFFFFFu, x, off);
            if (lane >= off) x += u;
        }
        wt[lane] = x;
    }
    __syncthreads();
    int incl = v + (w ? wt[w - 1] : 0);
    int excl = incl - s;
#pragma unroll
    for (int j = 0; j < 8; j++) {
        g_rowstart[base + j] = excl + loc[j];
        int d = g_degi[base + j];
        g_rdeg[base + j] = 1.0f / (float)max(d, 1);
    }
    if (t == 1023) g_rowstart[NN] = incl;
}

__global__ void fill_kernel(int n_edges) {
    int i = blockIdx.x * blockDim.x + threadIdx.x;
    if (i >= n_edges) return;
    int d = g_dst[i];
    int p = atomicAdd(&g_cursor[d], 1);
    g_csr[g_rowstart[d] + p] = g_src[i];
}

// ---------------- aggregation (warp per node, gather over CSR) ---------------

__global__ void agg128_kernel(const float* __restrict__ x, float* __restrict__ out) {
    int w = (blockIdx.x * blockDim.x + threadIdx.x) >> 5;
    if (w >= NN) return;
    int lane = threadIdx.x & 31;
    int beg = g_rowstart[w], end = g_rowstart[w + 1];
    float4 acc = make_float4(0.f, 0.f, 0.f, 0.f);
    int j = beg;
    for (; j + 4 <= end; j += 4) {
        int s0 = g_csr[j], s1 = g_csr[j + 1], s2 = g_csr[j + 2], s3 = g_csr[j + 3];
        float4 v0 = *(const float4*)&x[s0 * IND + lane * 4];
        float4 v1 = *(const float4*)&x[s1 * IND + lane * 4];
        float4 v2 = *(const float4*)&x[s2 * IND + lane * 4];
        float4 v3 = *(const float4*)&x[s3 * IND + lane * 4];
        acc.x += v0.x + v1.x + v2.x + v3.x;
        acc.y += v0.y + v1.y + v2.y + v3.y;
        acc.z += v0.z + v1.z + v2.z + v3.z;
        acc.w += v0.w + v1.w + v2.w + v3.w;
    }
    for (; j < end; j++) {
        int s0 = g_csr[j];
        float4 v0 = *(const float4*)&x[s0 * IND + lane * 4];
        acc.x += v0.x; acc.y += v0.y; acc.z += v0.z; acc.w += v0.w;
    }
    float r = g_rdeg[w];
    acc.x *= r; acc.y *= r; acc.z *= r; acc.w *= r;
    *(float4*)&out[w * IND + lane * 4] = acc;
}

__global__ void agg256_kernel(const float* __restrict__ x, float* __restrict__ out) {
    int w = (blockIdx.x * blockDim.x + threadIdx.x) >> 5;
    if (w >= NN) return;
    int lane = threadIdx.x & 31;
    int beg = g_rowstart[w], end = g_rowstart[w + 1];
    float4 accA = make_float4(0.f, 0.f, 0.f, 0.f);
    float4 accB = make_float4(0.f, 0.f, 0.f, 0.f);
    int j = beg;
    for (; j + 4 <= end; j += 4) {
        int s0 = g_csr[j], s1 = g_csr[j + 1], s2 = g_csr[j + 2], s3 = g_csr[j + 3];
        float4 a0 = *(const float4*)&x[s0 * HID + lane * 4];
        float4 b0 = *(const float4*)&x[s0 * HID + 128 + lane * 4];
        float4 a1 = *(const float4*)&x[s1 * HID + lane * 4];
        float4 b1 = *(const float4*)&x[s1 * HID + 128 + lane * 4];
        float4 a2 = *(const float4*)&x[s2 * HID + lane * 4];
        float4 b2 = *(const float4*)&x[s2 * HID + 128 + lane * 4];
        float4 a3 = *(const float4*)&x[s3 * HID + lane * 4];
        float4 b3 = *(const float4*)&x[s3 * HID + 128 + lane * 4];
        accA.x += (a0.x + a1.x) + (a2.x + a3.x);
        accA.y += (a0.y + a1.y) + (a2.y + a3.y);
        accA.z += (a0.z + a1.z) + (a2.z + a3.z);
        accA.w += (a0.w + a1.w) + (a2.w + a3.w);
        accB.x += (b0.x + b1.x) + (b2.x + b3.x);
        accB.y += (b0.y + b1.y) + (b2.y + b3.y);
        accB.z += (b0.z + b1.z) + (b2.z + b3.z);
        accB.w += (b0.w + b1.w) + (b2.w + b3.w);
    }
    for (; j < end; j++) {
        int s0 = g_csr[j];
        float4 a0 = *(const float4*)&x[s0 * HID + lane * 4];
        float4 b0 = *(const float4*)&x[s0 * HID + 128 + lane * 4];
        accA.x += a0.x; accA.y += a0.y; accA.z += a0.z; accA.w += a0.w;
        accB.x += b0.x; accB.y += b0.y; accB.z += b0.z; accB.w += b0.w;
    }
    float r = g_rdeg[w];
    accA.x *= r; accA.y *= r; accA.z *= r; accA.w *= r;
    accB.x *= r; accB.y *= r; accB.z *= r; accB.w *= r;
    *(float4*)&out[w * HID + lane * 4] = accA;
    *(float4*)&out[w * HID + 128 + lane * 4] = accB;
}

// ---------------- dual-operand GEMM: C = relu(A1@W1.T + A2@W2.T + bias) ------
// Block tile 128x128, 256 threads, 8x8 microtile, BK=8, smem double-buffered.

template <int K, bool RELU>
__global__ __launch_bounds__(256) void gemm2_kernel(
    const float* __restrict__ A1, const float* __restrict__ W1,
    const float* __restrict__ A2, const float* __restrict__ W2,
    const float* __restrict__ bias, float* __restrict__ C) {
    const int BK = 8;
    const int S = (2 * K) / BK;              // stages across both passes
    __shared__ float As[2][BK][132];
    __shared__ float Bs[2][BK][132];

    int t = threadIdx.x;
    int rowBase = blockIdx.x * 128;
    int colBase = blockIdx.y * 128;
    int tx = t & 15;         // N dir
    int ty = t >> 4;         // M dir
    int lr = t >> 1;         // load row within tile (0..127)
    int lk = (t & 1) * 4;    // load k offset (0 or 4)

    float acc[8][8];
#pragma unroll
    for (int i = 0; i < 8; i++)
#pragma unroll
        for (int j = 0; j < 8; j++) acc[i][j] = 0.f;

    auto gload = [&](int s, float4& av, float4& bv) {
        int pass = (s * BK) / K;
        int k0 = (s * BK) % K;
        const float* A = pass ? A2 : A1;
        const float* W = pass ? W2 : W1;
        av = *(const float4*)&A[(size_t)(rowBase + lr) * K + k0 + lk];
        bv = *(const float4*)&W[(size_t)(colBase + lr) * K + k0 + lk];
    };
    auto sstore = [&](int buf, const float4& av, const float4& bv) {
        As[buf][lk + 0][lr] = av.x; As[buf][lk + 1][lr] = av.y;
        As[buf][lk + 2][lr] = av.z; As[buf][lk + 3][lr] = av.w;
        Bs[buf][lk + 0][lr] = bv.x; Bs[buf][lk + 1][lr] = bv.y;
        Bs[buf][lk + 2][lr] = bv.z; Bs[buf][lk + 3][lr] = bv.w;
    };

    float4 av, bv;
    gload(0, av, bv);
    sstore(0, av, bv);
    __syncthreads();

    for (int s = 0; s < S; s++) {
        float4 nav, nbv;
        if (s + 1 < S) gload(s + 1, nav, nbv);
        int b = s & 1;
#pragma unroll
        for (int kk = 0; kk < BK; kk++) {
            float4 a0 = *(const float4*)&As[b][kk][ty * 4];
            float4 a1 = *(const float4*)&As[b][kk][64 + ty * 4];
            float4 b0 = *(const float4*)&Bs[b][kk][tx * 4];
            float4 b1 = *(const float4*)&Bs[b][kk][64 + tx * 4];
            float a[8] = {a0.x, a0.y, a0.z, a0.w, a1.x, a1.y, a1.z, a1.w};
            float bb[8] = {b0.x, b0.y, b0.z, b0.w, b1.x, b1.y, b1.z, b1.w};
#pragma unroll
            for (int i = 0; i < 8; i++)
#pragma unroll
                for (int j = 0; j < 8; j++) acc[i][j] += a[i] * bb[j];
        }
        if (s + 1 < S) {
            sstore(b ^ 1, nav, nbv);
            __syncthreads();
        }
    }

    // epilogue
#pragma unroll
    for (int i = 0; i < 8; i++) {
        int row = rowBase + ((i < 4) ? (ty * 4 + i) : (64 + ty * 4 + i - 4));
#pragma unroll
        for (int half = 0; half < 2; half++) {
            int col = colBase + (half ? (64 + tx * 4) : (tx * 4));
            float4 o;
            o.x = acc[i][half * 4 + 0] + bias[col + 0];
            o.y = acc[i][half * 4 + 1] + bias[col + 1];
            o.z = acc[i][half * 4 + 2] + bias[col + 2];
            o.w = acc[i][half * 4 + 3] + bias[col + 3];
            if (RELU) {
                o.x = fmaxf(o.x, 0.f); o.y = fmaxf(o.y, 0.f);
                o.z = fmaxf(o.z, 0.f); o.w = fmaxf(o.w, 0.f);
            }
            *(float4*)&C[(size_t)row * HID + col] = o;
        }
    }
}

// ---------------- final-layer algebra ----------------------------------------

__global__ void vprep_kernel(const float* __restrict__ w_out,
                             const float* __restrict__ b_out,
                             const float* __restrict__ w_edge) {
    int k = threadIdx.x;  // 256 threads
    float sl = 0.f, sr = 0.f;
    for (int o = 0; o < HID; o++) {
        float w = w_out[o * HID + k];
        sl += w * w_edge[o];
        sr += w * w_edge[HID + o];
    }
    g_vl[k] = sl;
    g_vr[k] = sr;
    if (k == 0) {
        float cl = 0.f, cr = 0.f;
        for (int o = 0; o < HID; o++) {
            cl += b_out[o] * w_edge[o];
            cr += b_out[o] * w_edge[HID + o];
        }
        g_cc[0] = cl;
        g_cc[1] = cr;
    }
}

__global__ void lilj_kernel(const float* __restrict__ h) {
    int w = (blockIdx.x * blockDim.x + threadIdx.x) >> 5;
    if (w >= NN) return;
    int lane = threadIdx.x & 31;
    int k = lane * 8;
    float4 p0 = *(const float4*)&h[(size_t)w * HID + k];
    float4 p1 = *(const float4*)&h[(size_t)w * HID + k + 4];
    float4 vl0 = *(const float4*)&g_vl[k];
    float4 vl1 = *(const float4*)&g_vl[k + 4];
    float4 vr0 = *(const float4*)&g_vr[k];
    float4 vr1 = *(const float4*)&g_vr[k + 4];
    float sl = p0.x * vl0.x + p0.y * vl0.y + p0.z * vl0.z + p0.w * vl0.w +
               p1.x * vl1.x + p1.y * vl1.y + p1.z * vl1.z + p1.w * vl1.w;
    float sr = p0.x * vr0.x + p0.y * vr0.y + p0.z * vr0.z + p0.w * vr0.w +
               p1.x * vr1.x + p1.y * vr1.y + p1.z * vr1.z + p1.w * vr1.w;
#pragma unroll
    for (int off = 16; off > 0; off >>= 1) {
        sl += __shfl_xor_sync(0xFFFFFFFFu, sl, off);
        sr += __shfl_xor_sync(0xFFFFFFFFu, sr, off);
    }
    if (lane == 0) {
        g_li[w] = sl + g_cc[0];
        g_lj[w] = sr + g_cc[1];
    }
}

// ---------------- rank-1 broadcast output ------------------------------------

__global__ __launch_bounds__(256) void out_kernel(float* __restrict__ out,
                                                  const float* __restrict__ b_edge) {
    __shared__ float slj[2048];
    __shared__ float sli[16];
    int colBase = blockIdx.x * 2048;
    int rowBase = blockIdx.y * 16;
    float be = b_edge[0];
    for (int c = threadIdx.x; c < 2048; c += 256) slj[c] = g_lj[colBase + c];
    if (threadIdx.x < 16) sli[threadIdx.x] = g_li[rowBase + threadIdx.x];
    __syncthreads();
#pragma unroll 4
    for (int r = 0; r < 16; r++) {
        float liv = sli[r] + be;
        size_t base = (size_t)(rowBase + r) * NN + colBase;
        for (int c = threadIdx.x; c < 512; c += 256) {
            float4 v = *(const float4*)&slj[c * 4];
            float4 o = make_float4(liv + v.x, liv + v.y, liv + v.z, liv + v.w);
            *(float4*)&out[base + c * 4] = o;
        }
    }
}

// ---------------- launcher ----------------------------------------------------

extern "C" void kernel_launch(void* const* d_in, const int* in_sizes, int n_in,
                              void* d_out, int out_size) {
    const float* x      = (const float*)d_in[0];
    const int*   edges  = (const int*)d_in[1];   // probed: int64 or int32
    const float* wl1    = (const float*)d_in[2];
    const float* bl1    = (const float*)d_in[3];
    const float* wr1    = (const float*)d_in[4];
    const float* wl2    = (const float*)d_in[5];
    const float* bl2    = (const float*)d_in[6];
    const float* wr2    = (const float*)d_in[7];
    const float* w_out  = (const float*)d_in[8];
    const float* b_out  = (const float*)d_in[9];
    const float* w_edge = (const float*)d_in[10];
    const float* b_edge = (const float*)d_in[11];
    float* out = (float*)d_out;

    int n_edges = NE;

    float* mean1 = nullptr; float* h1 = nullptr; float* mean2 = nullptr; float* h2 = nullptr;
    cudaGetSymbolAddress((void**)&mean1, g_mean1);
    cudaGetSymbolAddress((void**)&h1, g_h1);
    cudaGetSymbolAddress((void**)&mean2, g_mean2);
    cudaGetSymbolAddress((void**)&h2, g_h2);

    // graph build
    initprobe_kernel<<<33, 256>>>(edges);
    convert_kernel<<<(n_edges + 255) / 256, 256>>>(edges, n_edges);
    scan_kernel<<<1, 1024>>>();
    fill_kernel<<<(n_edges + 255) / 256, 256>>>(n_edges);

    // layer 1
    agg128_kernel<<<NN * 32 / 256, 256>>>(x, mean1);
    {
        dim3 grid(NN / 128, HID / 128);
        gemm2_kernel<IND, true><<<grid, 256>>>(mean1, wl1, x, wr1, bl1, h1);
    }
    // layer 2
    agg256_kernel<<<NN * 32 / 256, 256>>>(h1, mean2);
    {
        dim3 grid(NN / 128, HID / 128);
        gemm2_kernel<HID, true><<<grid, 256>>>(mean2, wl2, h1, wr2, bl2, h2);
    }
    // output head
    vprep_kernel<<<1, 256>>>(w_out, b_out, w_edge);
    lilj_kernel<<<NN * 32 / 256, 256>>>(h2);
    {
        dim3 grid(NN / 2048, NN / 16);
        out_kernel<<<grid, 256>>>(out, b_edge);
    }
}

// round 3
// speedup vs baseline: 1.6107x; 1.1717x over previous
#include <cuda_runtime.h>
#include <cuda_bf16.h>

#define NN 8192          // nodes
#define NE 262144        // edges
#define IND 128          // in dim
#define HID 256          // hidden

// ---------------- scratch (static device memory; no allocs allowed) ----------
__device__ int   g_is64;
__device__ int   g_src[NE];
__device__ int   g_dst[NE];
__device__ int   g_csr[NE];
__device__ int   g_rowstart[NN + 8];
__device__ int   g_degi[NN];
__device__ int   g_cursor[NN];        // pre-seeded with rowstart by scan_kernel
__device__ float g_rdeg[NN];
__device__ float g_mean1[NN * IND];     // 4 MB
__device__ float g_h1[NN * HID];        // 8 MB
__device__ float g_mean2[NN * HID];     // 8 MB
__device__ float g_h2[NN * HID];        // 8 MB
__device__ float g_li[NN];
__device__ float g_lj[NN];
__device__ float g_vl[HID];
__device__ float g_vr[HID];
__device__ float g_cc[2];

// ---------------- build chain ------------------------------------------------

// blocks 0..31 zero degi; block 32 probes int64 vs int32 layout.
__global__ void initprobe_kernel(const int* __restrict__ e) {
    if (blockIdx.x == 32) {
        __shared__ int any_nonzero;
        if (threadIdx.x == 0) any_nonzero = 0;
        __syncthreads();
        for (int i = threadIdx.x; i < 2048; i += blockDim.x) {
            if (e[2 * i + 1] != 0) any_nonzero = 1;
        }
        __syncthreads();
        if (threadIdx.x == 0) g_is64 = any_nonzero ? 0 : 1;
        return;
    }
    int i = blockIdx.x * blockDim.x + threadIdx.x;
    g_degi[i] = 0;
}

__global__ void convert_kernel(const int* __restrict__ e, int n_edges) {
    int i = blockIdx.x * blockDim.x + threadIdx.x;
    if (i >= n_edges) return;
    int s, d;
    if (g_is64) {
        s = e[2 * i];
        d = e[2 * (n_edges + i)];
    } else {
        s = e[i];
        d = e[n_edges + i];
    }
    g_src[i] = s;
    g_dst[i] = d;
    atomicAdd(&g_degi[d], 1);
}

// Exclusive prefix sum over g_degi (8192 entries), shuffle-based, 2 syncs.
// Also seeds g_cursor with rowstart so fill_kernel's atomic returns the
// absolute CSR slot (removes a dependent L2 load from fill's chain).
__global__ void scan_kernel() {
    int t = threadIdx.x;           // 1024 threads
    int lane = t & 31, w = t >> 5;
    int base = t * 8;
    int loc[8];
    int s = 0;
#pragma unroll
    for (int j = 0; j < 8; j++) { loc[j] = s; s += g_degi[base + j]; }
    int v = s;
#pragma unroll
    for (int off = 1; off < 32; off <<= 1) {
        int u = __shfl_up_sync(0xFFFFFFFFu, v, off);
        if (lane >= off) v += u;
    }
    __shared__ int wt[32];
    if (lane == 31) wt[w] = v;
    __syncthreads();
    if (w == 0) {
        int x = wt[lane];
#pragma unroll
        for (int off = 1; off < 32; off <<= 1) {
            int u = __shfl_up_sync(0xFFFFFFFFu, x, off);
            if (lane >= off) x += u;
        }
        wt[lane] = x;
    }
    __syncthreads();
    int incl = v + (w ? wt[w - 1] : 0);
    int excl = incl - s;
#pragma unroll
    for (int j = 0; j < 8; j++) {
        int rs = excl + loc[j];
        g_rowstart[base + j] = rs;
        g_cursor[base + j] = rs;
        int d = g_degi[base + j];
        g_rdeg[base + j] = 1.0f / (float)max(d, 1);
    }
    if (t == 1023) g_rowstart[NN] = incl;
}

__global__ void fill_kernel(int n_edges) {
    int i = blockIdx.x * blockDim.x + threadIdx.x;
    if (i >= n_edges) return;
    int d = g_dst[i];
    int p = atomicAdd(&g_cursor[d], 1);   // absolute slot (cursor seeded with rowstart)
    g_csr[p] = g_src[i];
}

// ---------------- aggregation (warp per node, gather over CSR) ---------------

__global__ void agg128_kernel(const float* __restrict__ x, float* __restrict__ out) {
    int w = (blockIdx.x * blockDim.x + threadIdx.x) >> 5;
    if (w >= NN) return;
    int lane = threadIdx.x & 31;
    int beg = g_rowstart[w], end = g_rowstart[w + 1];
    float4 acc = make_float4(0.f, 0.f, 0.f, 0.f);
    int j = beg;
    for (; j + 4 <= end; j += 4) {
        int s0 = g_csr[j], s1 = g_csr[j + 1], s2 = g_csr[j + 2], s3 = g_csr[j + 3];
        float4 v0 = *(const float4*)&x[s0 * IND + lane * 4];
        float4 v1 = *(const float4*)&x[s1 * IND + lane * 4];
        float4 v2 = *(const float4*)&x[s2 * IND + lane * 4];
        float4 v3 = *(const float4*)&x[s3 * IND + lane * 4];
        acc.x += (v0.x + v1.x) + (v2.x + v3.x);
        acc.y += (v0.y + v1.y) + (v2.y + v3.y);
        acc.z += (v0.z + v1.z) + (v2.z + v3.z);
        acc.w += (v0.w + v1.w) + (v2.w + v3.w);
    }
    for (; j < end; j++) {
        int s0 = g_csr[j];
        float4 v0 = *(const float4*)&x[s0 * IND + lane * 4];
        acc.x += v0.x; acc.y += v0.y; acc.z += v0.z; acc.w += v0.w;
    }
    float r = g_rdeg[w];
    acc.x *= r; acc.y *= r; acc.z *= r; acc.w *= r;
    *(float4*)&out[w * IND + lane * 4] = acc;
}

__global__ void agg256_kernel(const float* __restrict__ x, float* __restrict__ out) {
    int w = (blockIdx.x * blockDim.x + threadIdx.x) >> 5;
    if (w >= NN) return;
    int lane = threadIdx.x & 31;
    int beg = g_rowstart[w], end = g_rowstart[w + 1];
    float4 accA = make_float4(0.f, 0.f, 0.f, 0.f);
    float4 accB = make_float4(0.f, 0.f, 0.f, 0.f);
    int j = beg;
    for (; j + 4 <= end; j += 4) {
        int s0 = g_csr[j], s1 = g_csr[j + 1], s2 = g_csr[j + 2], s3 = g_csr[j + 3];
        float4 a0 = *(const float4*)&x[s0 * HID + lane * 4];
        float4 b0 = *(const float4*)&x[s0 * HID + 128 + lane * 4];
        float4 a1 = *(const float4*)&x[s1 * HID + lane * 4];
        float4 b1 = *(const float4*)&x[s1 * HID + 128 + lane * 4];
        float4 a2 = *(const float4*)&x[s2 * HID + lane * 4];
        float4 b2 = *(const float4*)&x[s2 * HID + 128 + lane * 4];
        float4 a3 = *(const float4*)&x[s3 * HID + lane * 4];
        float4 b3 = *(const float4*)&x[s3 * HID + 128 + lane * 4];
        accA.x += (a0.x + a1.x) + (a2.x + a3.x);
        accA.y += (a0.y + a1.y) + (a2.y + a3.y);
        accA.z += (a0.z + a1.z) + (a2.z + a3.z);
        accA.w += (a0.w + a1.w) + (a2.w + a3.w);
        accB.x += (b0.x + b1.x) + (b2.x + b3.x);
        accB.y += (b0.y + b1.y) + (b2.y + b3.y);
        accB.z += (b0.z + b1.z) + (b2.z + b3.z);
        accB.w += (b0.w + b1.w) + (b2.w + b3.w);
    }
    for (; j < end; j++) {
        int s0 = g_csr[j];
        float4 a0 = *(const float4*)&x[s0 * HID + lane * 4];
        float4 b0 = *(const float4*)&x[s0 * HID + 128 + lane * 4];
        accA.x += a0.x; accA.y += a0.y; accA.z += a0.z; accA.w += a0.w;
        accB.x += b0.x; accB.y += b0.y; accB.z += b0.z; accB.w += b0.w;
    }
    float r = g_rdeg[w];
    accA.x *= r; accA.y *= r; accA.z *= r; accA.w *= r;
    accB.x *= r; accB.y *= r; accB.z *= r; accB.w *= r;
    *(float4*)&out[w * HID + lane * 4] = accA;
    *(float4*)&out[w * HID + 128 + lane * 4] = accB;
}

// ---------------- dual-operand GEMM: C = relu(A1@W1.T + A2@W2.T + bias) ------
// Block tile 128x128, 256 threads, 8x8 microtile, BK=16, smem double-buffered.

template <int K, bool RELU>
__global__ __launch_bounds__(256) void gemm2_kernel(
    const float* __restrict__ A1, const float* __restrict__ W1,
    const float* __restrict__ A2, const float* __restrict__ W2,
    const float* __restrict__ bias, float* __restrict__ C) {
    const int BK = 16;
    const int S = (2 * K) / BK;              // stages across both passes
    __shared__ float As[2][BK][132];
    __shared__ float Bs[2][BK][132];

    int t = threadIdx.x;
    int rowBase = blockIdx.x * 128;
    int colBase = blockIdx.y * 128;
    int tx = t & 15;         // N dir
    int ty = t >> 4;         // M dir
    int lr = t >> 1;         // load row within tile (0..127)
    int lk = (t & 1) * 8;    // load k offset (0 or 8)

    float acc[8][8];
#pragma unroll
    for (int i = 0; i < 8; i++)
#pragma unroll
        for (int j = 0; j < 8; j++) acc[i][j] = 0.f;

    auto gload = [&](int s, float4& av0, float4& av1, float4& bv0, float4& bv1) {
        int pass = (s * BK) / K;
        int k0 = (s * BK) % K;
        const float* A = pass ? A2 : A1;
        const float* W = pass ? W2 : W1;
        const float* ap = &A[(size_t)(rowBase + lr) * K + k0 + lk];
        const float* wp = &W[(size_t)(colBase + lr) * K + k0 + lk];
        av0 = *(const float4*)ap;
        av1 = *(const float4*)(ap + 4);
        bv0 = *(const float4*)wp;
        bv1 = *(const float4*)(wp + 4);
    };
    auto sstore = [&](int buf, const float4& av0, const float4& av1,
                      const float4& bv0, const float4& bv1) {
        As[buf][lk + 0][lr] = av0.x; As[buf][lk + 1][lr] = av0.y;
        As[buf][lk + 2][lr] = av0.z; As[buf][lk + 3][lr] = av0.w;
        As[buf][lk + 4][lr] = av1.x; As[buf][lk + 5][lr] = av1.y;
        As[buf][lk + 6][lr] = av1.z; As[buf][lk + 7][lr] = av1.w;
        Bs[buf][lk + 0][lr] = bv0.x; Bs[buf][lk + 1][lr] = bv0.y;
        Bs[buf][lk + 2][lr] = bv0.z; Bs[buf][lk + 3][lr] = bv0.w;
        Bs[buf][lk + 4][lr] = bv1.x; Bs[buf][lk + 5][lr] = bv1.y;
        Bs[buf][lk + 6][lr] = bv1.z; Bs[buf][lk + 7][lr] = bv1.w;
    };

    float4 av0, av1, bv0, bv1;
    gload(0, av0, av1, bv0, bv1);
    sstore(0, av0, av1, bv0, bv1);
    __syncthreads();

    for (int s = 0; s < S; s++) {
        float4 nav0, nav1, nbv0, nbv1;
        if (s + 1 < S) gload(s + 1, nav0, nav1, nbv0, nbv1);
        int b = s & 1;
#pragma unroll
        for (int kk = 0; kk < BK; kk++) {
            float4 a0 = *(const float4*)&As[b][kk][ty * 4];
            float4 a1 = *(const float4*)&As[b][kk][64 + ty * 4];
            float4 b0 = *(const float4*)&Bs[b][kk][tx * 4];
            float4 b1 = *(const float4*)&Bs[b][kk][64 + tx * 4];
            float a[8] = {a0.x, a0.y, a0.z, a0.w, a1.x, a1.y, a1.z, a1.w};
            float bb[8] = {b0.x, b0.y, b0.z, b0.w, b1.x, b1.y, b1.z, b1.w};
#pragma unroll
            for (int i = 0; i < 8; i++)
#pragma unroll
                for (int j = 0; j < 8; j++) acc[i][j] += a[i] * bb[j];
        }
        if (s + 1 < S) {
            sstore(b ^ 1, nav0, nav1, nbv0, nbv1);
            __syncthreads();
        }
    }

    // epilogue
#pragma unroll
    for (int i = 0; i < 8; i++) {
        int row = rowBase + ((i < 4) ? (ty * 4 + i) : (64 + ty * 4 + i - 4));
#pragma unroll
        for (int half = 0; half < 2; half++) {
            int col = colBase + (half ? (64 + tx * 4) : (tx * 4));
            float4 o;
            o.x = acc[i][half * 4 + 0] + bias[col + 0];
            o.y = acc[i][half * 4 + 1] + bias[col + 1];
            o.z = acc[i][half * 4 + 2] + bias[col + 2];
            o.w = acc[i][half * 4 + 3] + bias[col + 3];
            if (RELU) {
                o.x = fmaxf(o.x, 0.f); o.y = fmaxf(o.y, 0.f);
                o.z = fmaxf(o.z, 0.f); o.w = fmaxf(o.w, 0.f);
            }
            *(float4*)&C[(size_t)row * HID + col] = o;
        }
    }
}

// ---------------- final-layer algebra ----------------------------------------

__global__ void vprep_kernel(const float* __restrict__ w_out,
                             const float* __restrict__ b_out,
                             const float* __restrict__ w_edge) {
    int k = threadIdx.x;  // 256 threads
    float sl = 0.f, sr = 0.f;
    for (int o = 0; o < HID; o++) {
        float w = w_out[o * HID + k];
        sl += w * w_edge[o];
        sr += w * w_edge[HID + o];
    }
    g_vl[k] = sl;
    g_vr[k] = sr;
    if (k == 0) {
        float cl = 0.f, cr = 0.f;
        for (int o = 0; o < HID; o++) {
            cl += b_out[o] * w_edge[o];
            cr += b_out[o] * w_edge[HID + o];
        }
        g_cc[0] = cl;
        g_cc[1] = cr;
    }
}

__global__ void lilj_kernel(const float* __restrict__ h) {
    int w = (blockIdx.x * blockDim.x + threadIdx.x) >> 5;
    if (w >= NN) return;
    int lane = threadIdx.x & 31;
    int k = lane * 8;
    float4 p0 = *(const float4*)&h[(size_t)w * HID + k];
    float4 p1 = *(const float4*)&h[(size_t)w * HID + k + 4];
    float4 vl0 = *(const float4*)&g_vl[k];
    float4 vl1 = *(const float4*)&g_vl[k + 4];
    float4 vr0 = *(const float4*)&g_vr[k];
    float4 vr1 = *(const float4*)&g_vr[k + 4];
    float sl = p0.x * vl0.x + p0.y * vl0.y + p0.z * vl0.z + p0.w * vl0.w +
               p1.x * vl1.x + p1.y * vl1.y + p1.z * vl1.z + p1.w * vl1.w;
    float sr = p0.x * vr0.x + p0.y * vr0.y + p0.z * vr0.z + p0.w * vr0.w +
               p1.x * vr1.x + p1.y * vr1.y + p1.z * vr1.z + p1.w * vr1.w;
#pragma unroll
    for (int off = 16; off > 0; off >>= 1) {
        sl += __shfl_xor_sync(0xFFFFFFFFu, sl, off);
        sr += __shfl_xor_sync(0xFFFFFFFFu, sr, off);
    }
    if (lane == 0) {
        g_li[w] = sl + g_cc[0];
        g_lj[w] = sr + g_cc[1];
    }
}

// ---------------- rank-1 broadcast output ------------------------------------

__global__ __launch_bounds__(256) void out_kernel(float* __restrict__ out,
                                                  const float* __restrict__ b_edge) {
    __shared__ float slj[2048];
    __shared__ float sli[16];
    int colBase = blockIdx.x * 2048;
    int rowBase = blockIdx.y * 16;
    float be = b_edge[0];
    for (int c = threadIdx.x; c < 2048; c += 256) slj[c] = g_lj[colBase + c];
    if (threadIdx.x < 16) sli[threadIdx.x] = g_li[rowBase + threadIdx.x];
    __syncthreads();
#pragma unroll 4
    for (int r = 0; r < 16; r++) {
        float liv = sli[r] + be;
        size_t base = (size_t)(rowBase + r) * NN + colBase;
        for (int c = threadIdx.x; c < 512; c += 256) {
            float4 v = *(const float4*)&slj[c * 4];
            float4 o = make_float4(liv + v.x, liv + v.y, liv + v.z, liv + v.w);
            __stcs((float4*)&out[base + c * 4], o);
        }
    }
}

// ---------------- launcher ----------------------------------------------------

extern "C" void kernel_launch(void* const* d_in, const int* in_sizes, int n_in,
                              void* d_out, int out_size) {
    const float* x      = (const float*)d_in[0];
    const int*   edges  = (const int*)d_in[1];   // probed: int64 or int32
    const float* wl1    = (const float*)d_in[2];
    const float* bl1    = (const float*)d_in[3];
    const float* wr1    = (const float*)d_in[4];
    const float* wl2    = (const float*)d_in[5];
    const float* bl2    = (const float*)d_in[6];
    const float* wr2    = (const float*)d_in[7];
    const float* w_out  = (const float*)d_in[8];
    const float* b_out  = (const float*)d_in[9];
    const float* w_edge = (const float*)d_in[10];
    const float* b_edge = (const float*)d_in[11];
    float* out = (float*)d_out;

    int n_edges = NE;

    float* mean1 = nullptr; float* h1 = nullptr; float* mean2 = nullptr; float* h2 = nullptr;
    cudaGetSymbolAddress((void**)&mean1, g_mean1);
    cudaGetSymbolAddress((void**)&h1, g_h1);
    cudaGetSymbolAddress((void**)&mean2, g_mean2);
    cudaGetSymbolAddress((void**)&h2, g_h2);

    // graph build
    initprobe_kernel<<<33, 256>>>(edges);
    convert_kernel<<<(n_edges + 255) / 256, 256>>>(edges, n_edges);
    scan_kernel<<<1, 1024>>>();
    fill_kernel<<<(n_edges + 255) / 256, 256>>>(n_edges);

    // layer 1
    agg128_kernel<<<NN * 32 / 256, 256>>>(x, mean1);
    {
        dim3 grid(NN / 128, HID / 128);
        gemm2_kernel<IND, true><<<grid, 256>>>(mean1, wl1, x, wr1, bl1, h1);
    }
    // layer 2
    agg256_kernel<<<NN * 32 / 256, 256>>>(h1, mean2);
    {
        dim3 grid(NN / 128, HID / 128);
        gemm2_kernel<HID, true><<<grid, 256>>>(mean2, wl2, h1, wr2, bl2, h2);
    }
    // output head
    vprep_kernel<<<1, 256>>>(w_out, b_out, w_edge);
    lilj_kernel<<<NN * 32 / 256, 256>>>(h2);
    {
        dim3 grid(NN / 2048, NN / 16);
        out_kernel<<<grid, 256>>>(out, b_edge);
    }
}

// round 4
// speedup vs baseline: 1.8422x; 1.1437x over previous
#include <cuda_runtime.h>
#include <cuda_bf16.h>
#include <mma.h>
using namespace nvcuda;

#define NN 8192          // nodes
#define NE 262144        // edges
#define IND 128          // in dim
#define HID 256          // hidden

// ---------------- scratch (static device memory; no allocs allowed) ----------
__device__ int   g_is64;
__device__ int   g_src[NE];
__device__ int   g_dst[NE];
__device__ int   g_csr[NE];
__device__ int   g_rowstart[NN + 8];
__device__ int   g_degi[NN];
__device__ int   g_cursor[NN];
__device__ float g_rdeg[NN];

// bf16 split operands
__device__ __nv_bfloat16 g_xh[NN * IND],  g_xl[NN * IND];
__device__ __nv_bfloat16 g_m1h[NN * IND], g_m1l[NN * IND];
__device__ __nv_bfloat16 g_h1h[NN * HID], g_h1l[NN * HID];
__device__ __nv_bfloat16 g_m2h[NN * HID], g_m2l[NN * HID];
__device__ __nv_bfloat16 g_wl1h[HID * IND], g_wl1l[HID * IND];
__device__ __nv_bfloat16 g_wr1h[HID * IND], g_wr1l[HID * IND];
__device__ __nv_bfloat16 g_wl2h[HID * HID], g_wl2l[HID * HID];
__device__ __nv_bfloat16 g_wr2h[HID * HID], g_wr2l[HID * HID];

__device__ float g_h2[NN * HID];        // 8 MB
__device__ float g_li[NN];
__device__ float g_lj[NN];
__device__ float g_vl[HID];
__device__ float g_vr[HID];
__device__ float g_cc[2];

// ---------------- helpers -----------------------------------------------------

__device__ __forceinline__ void split_store4(float4 v, __nv_bfloat16* dh,
                                             __nv_bfloat16* dl, int idx) {
    __nv_bfloat16 h0 = __float2bfloat16(v.x);
    __nv_bfloat16 h1 = __float2bfloat16(v.y);
    __nv_bfloat16 h2 = __float2bfloat16(v.z);
    __nv_bfloat16 h3 = __float2bfloat16(v.w);
    union { __nv_bfloat16 b[4]; uint2 u; } H, L;
    H.b[0] = h0; H.b[1] = h1; H.b[2] = h2; H.b[3] = h3;
    L.b[0] = __float2bfloat16(v.x - __bfloat162float(h0));
    L.b[1] = __float2bfloat16(v.y - __bfloat162float(h1));
    L.b[2] = __float2bfloat16(v.z - __bfloat162float(h2));
    L.b[3] = __float2bfloat16(v.w - __bfloat162float(h3));
    *(uint2*)&dh[idx] = H.u;
    *(uint2*)&dl[idx] = L.u;
}

__device__ __forceinline__ float4 rec4(const __nv_bfloat16* h,
                                       const __nv_bfloat16* l, int idx) {
    union { uint2 u; __nv_bfloat162 b2[2]; } H, L;
    H.u = *(const uint2*)&h[idx];
    L.u = *(const uint2*)&l[idx];
    float2 h0 = __bfloat1622float2(H.b2[0]);
    float2 h1 = __bfloat1622float2(H.b2[1]);
    float2 l0 = __bfloat1622float2(L.b2[0]);
    float2 l1 = __bfloat1622float2(L.b2[1]);
    return make_float4(h0.x + l0.x, h0.y + l0.y, h1.x + l1.x, h1.y + l1.y);
}

// ---------------- fused prep: degi zero / probe / weight cvt / x cvt ----------

__global__ void prep_kernel(const int* __restrict__ e, const float* __restrict__ x,
                            const float* __restrict__ wl1, const float* __restrict__ wr1,
                            const float* __restrict__ wl2, const float* __restrict__ wr2) {
    int b = blockIdx.x;
    int t = threadIdx.x;
    if (b < 32) {
        g_degi[b * 256 + t] = 0;
        return;
    }
    if (b == 32) {
        __shared__ int any_nonzero;
        if (t == 0) any_nonzero = 0;
        __syncthreads();
        for (int i = t; i < 2048; i += blockDim.x)
            if (e[2 * i + 1] != 0) any_nonzero = 1;
        __syncthreads();
        if (t == 0) g_is64 = any_nonzero ? 0 : 1;
        return;
    }
    if (b < 225) {   // weights: 192 blocks x 1024 elems
        int gi = (b - 33) * 1024 + t * 4;
        const float* src; __nv_bfloat16 *dh, *dl; int off;
        if (gi < 32768)       { src = wl1; dh = g_wl1h; dl = g_wl1l; off = gi; }
        else if (gi < 65536)  { src = wr1; dh = g_wr1h; dl = g_wr1l; off = gi - 32768; }
        else if (gi < 131072) { src = wl2; dh = g_wl2h; dl = g_wl2l; off = gi - 65536; }
        else                  { src = wr2; dh = g_wr2h; dl = g_wr2l; off = gi - 131072; }
        float4 v = *(const float4*)&src[off];
        split_store4(v, dh, dl, off);
        return;
    }
    // x conversion: 1024 blocks x 1024 elems
    int gi = (b - 225) * 1024 + t * 4;
    float4 v = *(const float4*)&x[gi];
    split_store4(v, g_xh, g_xl, gi);
}

// ---------------- edge decode + degree histogram (MLP=4) ----------------------

__global__ void convert_kernel(const int* __restrict__ e, int n_edges) {
    int i = (blockIdx.x * blockDim.x + threadIdx.x) * 4;
    if (i >= n_edges) return;
    int s0, s1, s2, s3, d0, d1, d2, d3;
    if (g_is64) {
        uint4 qa = *(const uint4*)&e[2 * i];
        uint4 qb = *(const uint4*)&e[2 * i + 4];
        s0 = qa.x; s1 = qa.z; s2 = qb.x; s3 = qb.z;
        uint4 qc = *(const uint4*)&e[2 * n_edges + 2 * i];
        uint4 qd = *(const uint4*)&e[2 * n_edges + 2 * i + 4];
        d0 = qc.x; d1 = qc.z; d2 = qd.x; d3 = qd.z;
    } else {
        uint4 qs = *(const uint4*)&e[i];
        uint4 qd = *(const uint4*)&e[n_edges + i];
        s0 = qs.x; s1 = qs.y; s2 = qs.z; s3 = qs.w;
        d0 = qd.x; d1 = qd.y; d2 = qd.z; d3 = qd.w;
    }
    *(int4*)&g_src[i] = make_int4(s0, s1, s2, s3);
    *(int4*)&g_dst[i] = make_int4(d0, d1, d2, d3);
    atomicAdd(&g_degi[d0], 1);
    atomicAdd(&g_degi[d1], 1);
    atomicAdd(&g_degi[d2], 1);
    atomicAdd(&g_degi[d3], 1);
}

// Exclusive prefix sum over g_degi; seeds cursor with rowstart.
__global__ void scan_kernel() {
    int t = threadIdx.x;           // 1024 threads
    int lane = t & 31, w = t >> 5;
    int base = t * 8;
    int loc[8];
    int s = 0;
#pragma unroll
    for (int j = 0; j < 8; j++) { loc[j] = s; s += g_degi[base + j]; }
    int v = s;
#pragma unroll
    for (int off = 1; off < 32; off <<= 1) {
        int u = __shfl_up_sync(0xFFFFFFFFu, v, off);
        if (lane >= off) v += u;
    }
    __shared__ int wt[32];
    if (lane == 31) wt[w] = v;
    __syncthreads();
    if (w == 0) {
        int x = wt[lane];
#pragma unroll
        for (int off = 1; off < 32; off <<= 1) {
            int u = __shfl_up_sync(0xFFFFFFFFu, x, off);
            if (lane >= off) x += u;
        }
        wt[lane] = x;
    }
    __syncthreads();
    int incl = v + (w ? wt[w - 1] : 0);
    int excl = incl - s;
#pragma unroll
    for (int j = 0; j < 8; j++) {
        int rs = excl + loc[j];
        g_rowstart[base + j] = rs;
        g_cursor[base + j] = rs;
        int d = g_degi[base + j];
        g_rdeg[base + j] = 1.0f / (float)max(d, 1);
    }
    if (t == 1023) g_rowstart[NN] = incl;
}

__global__ void fill_kernel(int n_edges) {
    int i = (blockIdx.x * blockDim.x + threadIdx.x) * 4;
    if (i >= n_edges) return;
    int4 d = *(const int4*)&g_dst[i];
    int4 s = *(const int4*)&g_src[i];
    int p0 = atomicAdd(&g_cursor[d.x], 1);
    int p1 = atomicAdd(&g_cursor[d.y], 1);
    int p2 = atomicAdd(&g_cursor[d.z], 1);
    int p3 = atomicAdd(&g_cursor[d.w], 1);
    g_csr[p0] = s.x;
    g_csr[p1] = s.y;
    g_csr[p2] = s.z;
    g_csr[p3] = s.w;
}

// ---------------- aggregation (warp per node) ---------------------------------

__global__ void agg128_kernel(const float* __restrict__ x) {
    int w = (blockIdx.x * blockDim.x + threadIdx.x) >> 5;
    if (w >= NN) return;
    int lane = threadIdx.x & 31;
    int beg = g_rowstart[w], end = g_rowstart[w + 1];
    float4 acc = make_float4(0.f, 0.f, 0.f, 0.f);
    int j = beg;
    for (; j + 4 <= end; j += 4) {
        int s0 = g_csr[j], s1 = g_csr[j + 1], s2 = g_csr[j + 2], s3 = g_csr[j + 3];
        float4 v0 = *(const float4*)&x[s0 * IND + lane * 4];
        float4 v1 = *(const float4*)&x[s1 * IND + lane * 4];
        float4 v2 = *(const float4*)&x[s2 * IND + lane * 4];
        float4 v3 = *(const float4*)&x[s3 * IND + lane * 4];
        acc.x += (v0.x + v1.x) + (v2.x + v3.x);
        acc.y += (v0.y + v1.y) + (v2.y + v3.y);
        acc.z += (v0.z + v1.z) + (v2.z + v3.z);
        acc.w += (v0.w + v1.w) + (v2.w + v3.w);
    }
    for (; j < end; j++) {
        int s0 = g_csr[j];
        float4 v0 = *(const float4*)&x[s0 * IND + lane * 4];
        acc.x += v0.x; acc.y += v0.y; acc.z += v0.z; acc.w += v0.w;
    }
    float r = g_rdeg[w];
    acc.x *= r; acc.y *= r; acc.z *= r; acc.w *= r;
    split_store4(acc, g_m1h, g_m1l, w * IND + lane * 4);
}

__global__ void agg256_kernel() {
    int w = (blockIdx.x * blockDim.x + threadIdx.x) >> 5;
    if (w >= NN) return;
    int lane = threadIdx.x & 31;
    int beg = g_rowstart[w], end = g_rowstart[w + 1];
    float4 accA = make_float4(0.f, 0.f, 0.f, 0.f);
    float4 accB = make_float4(0.f, 0.f, 0.f, 0.f);
    int cA = lane * 4, cB = lane * 4 + 128;
    int j = beg;
    for (; j + 4 <= end; j += 4) {
        int s0 = g_csr[j], s1 = g_csr[j + 1], s2 = g_csr[j + 2], s3 = g_csr[j + 3];
        float4 a0 = rec4(g_h1h, g_h1l, s0 * HID + cA);
        float4 b0 = rec4(g_h1h, g_h1l, s0 * HID + cB);
        float4 a1 = rec4(g_h1h, g_h1l, s1 * HID + cA);
        float4 b1 = rec4(g_h1h, g_h1l, s1 * HID + cB);
        float4 a2 = rec4(g_h1h, g_h1l, s2 * HID + cA);
        float4 b2 = rec4(g_h1h, g_h1l, s2 * HID + cB);
        float4 a3 = rec4(g_h1h, g_h1l, s3 * HID + cA);
        float4 b3 = rec4(g_h1h, g_h1l, s3 * HID + cB);
        accA.x += (a0.x + a1.x) + (a2.x + a3.x);
        accA.y += (a0.y + a1.y) + (a2.y + a3.y);
        accA.z += (a0.z + a1.z) + (a2.z + a3.z);
        accA.w += (a0.w + a1.w) + (a2.w + a3.w);
        accB.x += (b0.x + b1.x) + (b2.x + b3.x);
        accB.y += (b0.y + b1.y) + (b2.y + b3.y);
        accB.z += (b0.z + b1.z) + (b2.z + b3.z);
        accB.w += (b0.w + b1.w) + (b2.w + b3.w);
    }
    for (; j < end; j++) {
        int s0 = g_csr[j];
        float4 a0 = rec4(g_h1h, g_h1l, s0 * HID + cA);
        float4 b0 = rec4(g_h1h, g_h1l, s0 * HID + cB);
        accA.x += a0.x; accA.y += a0.y; accA.z += a0.z; accA.w += a0.w;
        accB.x += b0.x; accB.y += b0.y; accB.z += b0.z; accB.w += b0.w;
    }
    float r = g_rdeg[w];
    accA.x *= r; accA.y *= r; accA.z *= r; accA.w *= r;
    accB.x *= r; accB.y *= r; accB.z *= r; accB.w *= r;
    split_store4(accA, g_m2h, g_m2l, w * HID + cA);
    split_store4(accB, g_m2h, g_m2l, w * HID + cB);
}

// ---------------- split-bf16 tensor-core GEMM ---------------------------------
// C = relu(A1@W1.T + A2@W2.T + bias), split bf16 hi/lo, 3-product scheme.
// Block 128x128, 256 threads (8 warps, 2x4), warp tile 64x32 (4x2 wmma frags).

template <int K, bool BF16OUT>
__global__ __launch_bounds__(256) void gemmw_kernel(
    const __nv_bfloat16* __restrict__ A1h, const __nv_bfloat16* __restrict__ A1l,
    const __nv_bfloat16* __restrict__ W1h, const __nv_bfloat16* __restrict__ W1l,
    const __nv_bfloat16* __restrict__ A2h, const __nv_bfloat16* __restrict__ A2l,
    const __nv_bfloat16* __restrict__ W2h, const __nv_bfloat16* __restrict__ W2l,
    const float* __restrict__ bias,
    float* __restrict__ outF, __nv_bfloat16* __restrict__ outH,
    __nv_bfloat16* __restrict__ outL)
{
    const int BK = 32, LD = 40;
    const int S = 2 * K / BK;
    extern __shared__ char smraw[];
    __nv_bfloat16 (*Ah)[LD] = (__nv_bfloat16(*)[LD])(smraw);
    __nv_bfloat16 (*Al)[LD] = (__nv_bfloat16(*)[LD])(smraw + 10240);
    __nv_bfloat16 (*Bh)[LD] = (__nv_bfloat16(*)[LD])(smraw + 20480);
    __nv_bfloat16 (*Bl)[LD] = (__nv_bfloat16(*)[LD])(smraw + 30720);
    float (*Cst)[132] = (float(*)[132])(smraw);

    int t = threadIdx.x;
    int rowBase = blockIdx.x * 128, colBase = blockIdx.y * 128;
    int lr = t >> 1, lks = (t & 1) * 16;
    int wid = t >> 5, warpM = wid >> 2, warpN = wid & 3;

    wmma::fragment<wmma::accumulator, 16, 16, 16, float> acc[4][2];
#pragma unroll
    for (int i = 0; i < 4; i++)
#pragma unroll
        for (int j = 0; j < 2; j++) wmma::fill_fragment(acc[i][j], 0.f);

    uint4 rah[2], ral[2], rbh[2], rbl[2];
    auto gload = [&](int s) {
        int pass = (s * BK) / K;
        int k0 = (s * BK) % K;
        const __nv_bfloat16* pAh = (pass ? A2h : A1h) + (size_t)(rowBase + lr) * K + k0 + lks;
        const __nv_bfloat16* pAl = (pass ? A2l : A1l) + (size_t)(rowBase + lr) * K + k0 + lks;
        const __nv_bfloat16* pWh = (pass ? W2h : W1h) + (size_t)(colBase + lr) * K + k0 + lks;
        const __nv_bfloat16* pWl = (pass ? W2l : W1l) + (size_t)(colBase + lr) * K + k0 + lks;
        rah[0] = *(const uint4*)pAh;       rah[1] = *(const uint4*)(pAh + 8);
        ral[0] = *(const uint4*)pAl;       ral[1] = *(const uint4*)(pAl + 8);
        rbh[0] = *(const uint4*)pWh;       rbh[1] = *(const uint4*)(pWh + 8);
        rbl[0] = *(const uint4*)pWl;       rbl[1] = *(const uint4*)(pWl + 8);
    };
    auto sstore = [&]() {
        *(uint4*)&Ah[lr][lks] = rah[0];    *(uint4*)&Ah[lr][lks + 8] = rah[1];
        *(uint4*)&Al[lr][lks] = ral[0];    *(uint4*)&Al[lr][lks + 8] = ral[1];
        *(uint4*)&Bh[lr][lks] = rbh[0];    *(uint4*)&Bh[lr][lks + 8] = rbh[1];
        *(uint4*)&Bl[lr][lks] = rbl[0];    *(uint4*)&Bl[lr][lks + 8] = rbl[1];
    };
    auto compute = [&]() {
#pragma unroll
        for (int kk = 0; kk < BK; kk += 16) {
            wmma::fragment<wmma::matrix_a, 16, 16, 16, __nv_bfloat16, wmma::row_major> ah[4], al[4];
            wmma::fragment<wmma::matrix_b, 16, 16, 16, __nv_bfloat16, wmma::col_major> bh[2], bl[2];
#pragma unroll
            for (int i = 0; i < 4; i++) {
                wmma::load_matrix_sync(ah[i], &Ah[warpM * 64 + i * 16][kk], LD);
                wmma::load_matrix_sync(al[i], &Al[warpM * 64 + i * 16][kk], LD);
            }
#pragma unroll
            for (int j = 0; j < 2; j++) {
                wmma::load_matrix_sync(bh[j], &Bh[warpN * 32 + j * 16][kk], LD);
                wmma::load_matrix_sync(bl[j], &Bl[warpN * 32 + j * 16][kk], LD);
            }
#pragma unroll
            for (int i = 0; i < 4; i++)
#pragma unroll
                for (int j = 0; j < 2; j++) {
                    wmma::mma_sync(acc[i][j], ah[i], bh[j], acc[i][j]);
                    wmma::mma_sync(acc[i][j], ah[i], bl[j], acc[i][j]);
                    wmma::mma_sync(acc[i][j], al[i], bh[j], acc[i][j]);
                }
        }
    };

    gload(0);
    sstore();
    __syncthreads();
    for (int s = 0; s < S; s++) {
        if (s + 1 < S) gload(s + 1);
        compute();
        __syncthreads();
        if (s + 1 < S) {
            sstore();
            __syncthreads();
        }
    }

    // epilogue: stage fp32 result in smem, then bias+relu+(split)store
#pragma unroll
    for (int i = 0; i < 4; i++)
#pragma unroll
        for (int j = 0; j < 2; j++)
            wmma::store_matrix_sync(&Cst[warpM * 64 + i * 16][warpN * 32 + j * 16],
                                    acc[i][j], 132, wmma::mem_row_major);
    __syncthreads();

    int r = lr;
    int cb = (t & 1) * 64;
    size_t row = rowBase + r;
#pragma unroll
    for (int cc = 0; cc < 64; cc += 4) {
        int c = cb + cc;
        float4 v = *(float4*)&Cst[r][c];
        float4 bi = *(const float4*)&bias[colBase + c];
        float4 o;
        o.x = fmaxf(v.x + bi.x, 0.f);
        o.y = fmaxf(v.y + bi.y, 0.f);
        o.z = fmaxf(v.z + bi.z, 0.f);
        o.w = fmaxf(v.w + bi.w, 0.f);
        if (BF16OUT) {
            split_store4(o, outH, outL, (int)(row * HID + colBase + c));
        } else {
            *(float4*)&outF[row * HID + colBase + c] = o;
        }
    }
}

// ---------------- final-layer algebra ----------------------------------------

__global__ void vprep_kernel(const float* __restrict__ w_out,
                             const float* __restrict__ b_out,
                             const float* __restrict__ w_edge) {
    int k = threadIdx.x;  // 256 threads
    float sl = 0.f, sr = 0.f;
    for (int o = 0; o < HID; o++) {
        float w = w_out[o * HID + k];
        sl += w * w_edge[o];
        sr += w * w_edge[HID + o];
    }
    g_vl[k] = sl;
    g_vr[k] = sr;
    if (k == 0) {
        float cl = 0.f, cr = 0.f;
        for (int o = 0; o < HID; o++) {
            cl += b_out[o] * w_edge[o];
            cr += b_out[o] * w_edge[HID + o];
        }
        g_cc[0] = cl;
        g_cc[1] = cr;
    }
}

__global__ void lilj_kernel(const float* __restrict__ h) {
    int w = (blockIdx.x * blockDim.x + threadIdx.x) >> 5;
    if (w >= NN) return;
    int lane = threadIdx.x & 31;
    int k = lane * 8;
    float4 p0 = *(const float4*)&h[(size_t)w * HID + k];
    float4 p1 = *(const float4*)&h[(size_t)w * HID + k + 4];
    float4 vl0 = *(const float4*)&g_vl[k];
    float4 vl1 = *(const float4*)&g_vl[k + 4];
    float4 vr0 = *(const float4*)&g_vr[k];
    float4 vr1 = *(const float4*)&g_vr[k + 4];
    float sl = p0.x * vl0.x + p0.y * vl0.y + p0.z * vl0.z + p0.w * vl0.w +
               p1.x * vl1.x + p1.y * vl1.y + p1.z * vl1.z + p1.w * vl1.w;
    float sr = p0.x * vr0.x + p0.y * vr0.y + p0.z * vr0.z + p0.w * vr0.w +
               p1.x * vr1.x + p1.y * vr1.y + p1.z * vr1.z + p1.w * vr1.w;
#pragma unroll
    for (int off = 16; off > 0; off >>= 1) {
        sl += __shfl_xor_sync(0xFFFFFFFFu, sl, off);
        sr += __shfl_xor_sync(0xFFFFFFFFu, sr, off);
    }
    if (lane == 0) {
        g_li[w] = sl + g_cc[0];
        g_lj[w] = sr + g_cc[1];
    }
}

// ---------------- rank-1 broadcast output ------------------------------------

__global__ __launch_bounds__(256) void out_kernel(float* __restrict__ out,
                                                  const float* __restrict__ b_edge) {
    __shared__ float slj[2048];
    __shared__ float sli[16];
    int colBase = blockIdx.x * 2048;
    int rowBase = blockIdx.y * 16;
    float be = b_edge[0];
    for (int c = threadIdx.x; c < 2048; c += 256) slj[c] = g_lj[colBase + c];
    if (threadIdx.x < 16) sli[threadIdx.x] = g_li[rowBase + threadIdx.x];
    __syncthreads();
#pragma unroll 4
    for (int r = 0; r < 16; r++) {
        float liv = sli[r] + be;
        size_t base = (size_t)(rowBase + r) * NN + colBase;
        for (int c = threadIdx.x; c < 512; c += 256) {
            float4 v = *(const float4*)&slj[c * 4];
            float4 o = make_float4(liv + v.x, liv + v.y, liv + v.z, liv + v.w);
            __stcs((float4*)&out[base + c * 4], o);
        }
    }
}

// ---------------- launcher ----------------------------------------------------

extern "C" void kernel_launch(void* const* d_in, const int* in_sizes, int n_in,
                              void* d_out, int out_size) {
    const float* x      = (const float*)d_in[0];
    const int*   edges  = (const int*)d_in[1];   // probed: int64 or int32
    const float* wl1    = (const float*)d_in[2];
    const float* bl1    = (const float*)d_in[3];
    const float* wr1    = (const float*)d_in[4];
    const float* wl2    = (const float*)d_in[5];
    const float* bl2    = (const float*)d_in[6];
    const float* wr2    = (const float*)d_in[7];
    const float* w_out  = (const float*)d_in[8];
    const float* b_out  = (const float*)d_in[9];
    const float* w_edge = (const float*)d_in[10];
    const float* b_edge = (const float*)d_in[11];
    float* out = (float*)d_out;

    int n_edges = NE;
    const int GEMM_SMEM = 128 * 132 * 4;   // 67584 bytes

    static bool attr_set = false;
    if (!attr_set) {
        cudaFuncSetAttribute(gemmw_kernel<IND, true>,
                             cudaFuncAttributeMaxDynamicSharedMemorySize, GEMM_SMEM);
        cudaFuncSetAttribute(gemmw_kernel<HID, false>,
                             cudaFuncAttributeMaxDynamicSharedMemorySize, GEMM_SMEM);
        attr_set = true;
    }

    __nv_bfloat16 *xh, *xl, *m1h, *m1l, *h1h, *h1l, *m2h, *m2l;
    __nv_bfloat16 *wl1h, *wl1l, *wr1h, *wr1l, *wl2h, *wl2l, *wr2h, *wr2l;
    float* h2;
    cudaGetSymbolAddress((void**)&xh, g_xh);   cudaGetSymbolAddress((void**)&xl, g_xl);
    cudaGetSymbolAddress((void**)&m1h, g_m1h); cudaGetSymbolAddress((void**)&m1l, g_m1l);
    cudaGetSymbolAddress((void**)&h1h, g_h1h); cudaGetSymbolAddress((void**)&h1l, g_h1l);
    cudaGetSymbolAddress((void**)&m2h, g_m2h); cudaGetSymbolAddress((void**)&m2l, g_m2l);
    cudaGetSymbolAddress((void**)&wl1h, g_wl1h); cudaGetSymbolAddress((void**)&wl1l, g_wl1l);
    cudaGetSymbolAddress((void**)&wr1h, g_wr1h); cudaGetSymbolAddress((void**)&wr1l, g_wr1l);
    cudaGetSymbolAddress((void**)&wl2h, g_wl2h); cudaGetSymbolAddress((void**)&wl2l, g_wl2l);
    cudaGetSymbolAddress((void**)&wr2h, g_wr2h); cudaGetSymbolAddress((void**)&wr2l, g_wr2l);
    cudaGetSymbolAddress((void**)&h2, g_h2);

    // prep: degi zero (32) + probe (1) + weight cvt (192) + x cvt (1024)
    prep_kernel<<<1249, 256>>>(edges, x, wl1, wr1, wl2, wr2);
    convert_kernel<<<NE / 1024, 256>>>(edges, n_edges);
    scan_kernel<<<1, 1024>>>();
    fill_kernel<<<NE / 1024, 256>>>(n_edges);

    // layer 1
    agg128_kernel<<<NN * 32 / 256, 256>>>(x);
    {
        dim3 grid(NN / 128, HID / 128);
        gemmw_kernel<IND, true><<<grid, 256, GEMM_SMEM>>>(
            m1h, m1l, wl1h, wl1l, xh, xl, wr1h, wr1l, bl1, nullptr, h1h, h1l);
    }
    // layer 2
    agg256_kernel<<<NN * 32 / 256, 256>>>();
    {
        dim3 grid(NN / 128, HID / 128);
        gemmw_kernel<HID, false><<<grid, 256, GEMM_SMEM>>>(
            m2h, m2l, wl2h, wl2l, h1h, h1l, wr2h, wr2l, bl2, h2, nullptr, nullptr);
    }
    // output head
    vprep_kernel<<<1, 256>>>(w_out, b_out, w_edge);
    lilj_kernel<<<NN * 32 / 256, 256>>>(h2);
    {
        dim3 grid(NN / 2048, NN / 16);
        out_kernel<<<grid, 256>>>(out, b_edge);
    }
}

// round 6
// speedup vs baseline: 1.8964x; 1.0294x over previous
#include <cuda_runtime.h>
#include <cuda_bf16.h>
#include <mma.h>
#include <cstdint>
using namespace nvcuda;

#define NN 8192          // nodes
#define NE 262144        // edges
#define IND 128          // in dim
#define HID 256          // hidden

// ---------------- scratch (static device memory; no allocs allowed) ----------
__device__ int   g_is64;
__device__ int   g_src[NE];
__device__ int   g_dst[NE];
__device__ int   g_csr[NE];
__device__ int   g_rowstart[NN + 8];
__device__ int   g_degi[NN];
__device__ int   g_cursor[NN];
__device__ float g_rdeg[NN];

// bf16 split operands
__device__ __nv_bfloat16 g_xh[NN * IND],  g_xl[NN * IND];
__device__ __nv_bfloat16 g_m1h[NN * IND], g_m1l[NN * IND];
__device__ __nv_bfloat16 g_h1h[NN * HID], g_h1l[NN * HID];
__device__ __nv_bfloat16 g_m2h[NN * HID], g_m2l[NN * HID];
__device__ __nv_bfloat16 g_wl1h[HID * IND], g_wl1l[HID * IND];
__device__ __nv_bfloat16 g_wr1h[HID * IND], g_wr1l[HID * IND];
__device__ __nv_bfloat16 g_wl2h[HID * HID], g_wl2l[HID * HID];
__device__ __nv_bfloat16 g_wr2h[HID * HID], g_wr2l[HID * HID];

__device__ float g_h2[NN * HID];        // 8 MB
__device__ float g_li[NN];
__device__ float g_lj[NN];
__device__ float g_vl[HID];
__device__ float g_vr[HID];
__device__ float g_cc[2];

// ---------------- helpers -----------------------------------------------------

__device__ __forceinline__ void split_store4(float4 v, __nv_bfloat16* dh,
                                             __nv_bfloat16* dl, int idx) {
    __nv_bfloat16 h0 = __float2bfloat16(v.x);
    __nv_bfloat16 h1 = __float2bfloat16(v.y);
    __nv_bfloat16 h2 = __float2bfloat16(v.z);
    __nv_bfloat16 h3 = __float2bfloat16(v.w);
    union { __nv_bfloat16 b[4]; uint2 u; } H, L;
    H.b[0] = h0; H.b[1] = h1; H.b[2] = h2; H.b[3] = h3;
    L.b[0] = __float2bfloat16(v.x - __bfloat162float(h0));
    L.b[1] = __float2bfloat16(v.y - __bfloat162float(h1));
    L.b[2] = __float2bfloat16(v.z - __bfloat162float(h2));
    L.b[3] = __float2bfloat16(v.w - __bfloat162float(h3));
    *(uint2*)&dh[idx] = H.u;
    *(uint2*)&dl[idx] = L.u;
}

__device__ __forceinline__ float4 rec4(const __nv_bfloat16* h,
                                       const __nv_bfloat16* l, int idx) {
    union { uint2 u; __nv_bfloat162 b2[2]; } H, L;
    H.u = *(const uint2*)&h[idx];
    L.u = *(const uint2*)&l[idx];
    float2 h0 = __bfloat1622float2(H.b2[0]);
    float2 h1 = __bfloat1622float2(H.b2[1]);
    float2 l0 = __bfloat1622float2(L.b2[0]);
    float2 l1 = __bfloat1622float2(L.b2[1]);
    return make_float4(h0.x + l0.x, h0.y + l0.y, h1.x + l1.x, h1.y + l1.y);
}

__device__ __forceinline__ void cpa16(unsigned dst, const void* src) {
    asm volatile("cp.async.cg.shared.global [%0], [%1], 16;\n" :: "r"(dst), "l"(src));
}
__device__ __forceinline__ void cpa_commit() {
    asm volatile("cp.async.commit_group;\n");
}
template <int N>
__device__ __forceinline__ void cpa_wait() {
    asm volatile("cp.async.wait_group %0;\n" :: "n"(N));
}

// ---------------- fused prep: degi zero / probe / weight cvt / x cvt ----------

__global__ void prep_kernel(const int* __restrict__ e, const float* __restrict__ x,
                            const float* __restrict__ wl1, const float* __restrict__ wr1,
                            const float* __restrict__ wl2, const float* __restrict__ wr2) {
    int b = blockIdx.x;
    int t = threadIdx.x;
    if (b < 32) {
        g_degi[b * 256 + t] = 0;
        return;
    }
    if (b == 32) {
        __shared__ int any_nonzero;
        if (t == 0) any_nonzero = 0;
        __syncthreads();
        for (int i = t; i < 2048; i += blockDim.x)
            if (e[2 * i + 1] != 0) any_nonzero = 1;
        __syncthreads();
        if (t == 0) g_is64 = any_nonzero ? 0 : 1;
        return;
    }
    if (b < 225) {   // weights: 192 blocks x 1024 elems
        int gi = (b - 33) * 1024 + t * 4;
        const float* src; __nv_bfloat16 *dh, *dl; int off;
        if (gi < 32768)       { src = wl1; dh = g_wl1h; dl = g_wl1l; off = gi; }
        else if (gi < 65536)  { src = wr1; dh = g_wr1h; dl = g_wr1l; off = gi - 32768; }
        else if (gi < 131072) { src = wl2; dh = g_wl2h; dl = g_wl2l; off = gi - 65536; }
        else                  { src = wr2; dh = g_wr2h; dl = g_wr2l; off = gi - 131072; }
        float4 v = *(const float4*)&src[off];
        split_store4(v, dh, dl, off);
        return;
    }
    // x conversion: 1024 blocks x 1024 elems
    int gi = (b - 225) * 1024 + t * 4;
    float4 v = *(const float4*)&x[gi];
    split_store4(v, g_xh, g_xl, gi);
}

// ---------------- edge decode + degree histogram (2 edges/thread) -------------

__global__ void convert_kernel(const int* __restrict__ e, int n_edges) {
    int i = (blockIdx.x * blockDim.x + threadIdx.x) * 2;
    if (i >= n_edges) return;
    int s0, s1, d0, d1;
    if (g_is64) {
        uint4 qa = *(const uint4*)&e[2 * i];
        s0 = qa.x; s1 = qa.z;
        uint4 qc = *(const uint4*)&e[2 * n_edges + 2 * i];
        d0 = qc.x; d1 = qc.z;
    } else {
        int2 qs = *(const int2*)&e[i];
        int2 qd = *(const int2*)&e[n_edges + i];
        s0 = qs.x; s1 = qs.y;
        d0 = qd.x; d1 = qd.y;
    }
    *(int2*)&g_src[i] = make_int2(s0, s1);
    *(int2*)&g_dst[i] = make_int2(d0, d1);
    atomicAdd(&g_degi[d0], 1);
    atomicAdd(&g_degi[d1], 1);
}

// Exclusive prefix sum over g_degi; seeds cursor with rowstart.
__global__ void scan_kernel() {
    int t = threadIdx.x;           // 1024 threads
    int lane = t & 31, w = t >> 5;
    int base = t * 8;
    int loc[8];
    int s = 0;
#pragma unroll
    for (int j = 0; j < 8; j++) { loc[j] = s; s += g_degi[base + j]; }
    int v = s;
#pragma unroll
    for (int off = 1; off < 32; off <<= 1) {
        int u = __shfl_up_sync(0xFFFFFFFFu, v, off);
        if (lane >= off) v += u;
    }
    __shared__ int wt[32];
    if (lane == 31) wt[w] = v;
    __syncthreads();
    if (w == 0) {
        int x = wt[lane];
#pragma unroll
        for (int off = 1; off < 32; off <<= 1) {
            int u = __shfl_up_sync(0xFFFFFFFFu, x, off);
            if (lane >= off) x += u;
        }
        wt[lane] = x;
    }
    __syncthreads();
    int incl = v + (w ? wt[w - 1] : 0);
    int excl = incl - s;
#pragma unroll
    for (int j = 0; j < 8; j++) {
        int rs = excl + loc[j];
        g_rowstart[base + j] = rs;
        g_cursor[base + j] = rs;
        int d = g_degi[base + j];
        g_rdeg[base + j] = 1.0f / (float)max(d, 1);
    }
    if (t == 1023) g_rowstart[NN] = incl;
}

__global__ void fill_kernel(int n_edges) {
    int i = (blockIdx.x * blockDim.x + threadIdx.x) * 2;
    if (i >= n_edges) return;
    int2 d = *(const int2*)&g_dst[i];
    int2 s = *(const int2*)&g_src[i];
    int p0 = atomicAdd(&g_cursor[d.x], 1);
    int p1 = atomicAdd(&g_cursor[d.y], 1);
    g_csr[p0] = s.x;
    g_csr[p1] = s.y;
}

// ---------------- aggregation (warp per node) ---------------------------------

__global__ void agg128_kernel(const float* __restrict__ x) {
    int w = (blockIdx.x * blockDim.x + threadIdx.x) >> 5;
    if (w >= NN) return;
    int lane = threadIdx.x & 31;
    int beg = g_rowstart[w], end = g_rowstart[w + 1];
    float4 acc = make_float4(0.f, 0.f, 0.f, 0.f);
    int j = beg;
    for (; j + 4 <= end; j += 4) {
        int s0 = g_csr[j], s1 = g_csr[j + 1], s2 = g_csr[j + 2], s3 = g_csr[j + 3];
        float4 v0 = *(const float4*)&x[s0 * IND + lane * 4];
        float4 v1 = *(const float4*)&x[s1 * IND + lane * 4];
        float4 v2 = *(const float4*)&x[s2 * IND + lane * 4];
        float4 v3 = *(const float4*)&x[s3 * IND + lane * 4];
        acc.x += (v0.x + v1.x) + (v2.x + v3.x);
        acc.y += (v0.y + v1.y) + (v2.y + v3.y);
        acc.z += (v0.z + v1.z) + (v2.z + v3.z);
        acc.w += (v0.w + v1.w) + (v2.w + v3.w);
    }
    for (; j < end; j++) {
        int s0 = g_csr[j];
        float4 v0 = *(const float4*)&x[s0 * IND + lane * 4];
        acc.x += v0.x; acc.y += v0.y; acc.z += v0.z; acc.w += v0.w;
    }
    float r = g_rdeg[w];
    acc.x *= r; acc.y *= r; acc.z *= r; acc.w *= r;
    split_store4(acc, g_m1h, g_m1l, w * IND + lane * 4);
}

__global__ void agg256_kernel() {
    int w = (blockIdx.x * blockDim.x + threadIdx.x) >> 5;
    if (w >= NN) return;
    int lane = threadIdx.x & 31;
    int beg = g_rowstart[w], end = g_rowstart[w + 1];
    float4 accA = make_float4(0.f, 0.f, 0.f, 0.f);
    float4 accB = make_float4(0.f, 0.f, 0.f, 0.f);
    int cA = lane * 4, cB = lane * 4 + 128;
    int j = beg;
    for (; j + 4 <= end; j += 4) {
        int s0 = g_csr[j], s1 = g_csr[j + 1], s2 = g_csr[j + 2], s3 = g_csr[j + 3];
        float4 a0 = rec4(g_h1h, g_h1l, s0 * HID + cA);
        float4 b0 = rec4(g_h1h, g_h1l, s0 * HID + cB);
        float4 a1 = rec4(g_h1h, g_h1l, s1 * HID + cA);
        float4 b1 = rec4(g_h1h, g_h1l, s1 * HID + cB);
        float4 a2 = rec4(g_h1h, g_h1l, s2 * HID + cA);
        float4 b2 = rec4(g_h1h, g_h1l, s2 * HID + cB);
        float4 a3 = rec4(g_h1h, g_h1l, s3 * HID + cA);
        float4 b3 = rec4(g_h1h, g_h1l, s3 * HID + cB);
        accA.x += (a0.x + a1.x) + (a2.x + a3.x);
        accA.y += (a0.y + a1.y) + (a2.y + a3.y);
        accA.z += (a0.z + a1.z) + (a2.z + a3.z);
        accA.w += (a0.w + a1.w) + (a2.w + a3.w);
        accB.x += (b0.x + b1.x) + (b2.x + b3.x);
        accB.y += (b0.y + b1.y) + (b2.y + b3.y);
        accB.z += (b0.z + b1.z) + (b2.z + b3.z);
        accB.w += (b0.w + b1.w) + (b2.w + b3.w);
    }
    for (; j < end; j++) {
        int s0 = g_csr[j];
        float4 a0 = rec4(g_h1h, g_h1l, s0 * HID + cA);
        float4 b0 = rec4(g_h1h, g_h1l, s0 * HID + cB);
        accA.x += a0.x; accA.y += a0.y; accA.z += a0.z; accA.w += a0.w;
        accB.x += b0.x; accB.y += b0.y; accB.z += b0.z; accB.w += b0.w;
    }
    float r = g_rdeg[w];
    accA.x *= r; accA.y *= r; accA.z *= r; accA.w *= r;
    accB.x *= r; accB.y *= r; accB.z *= r; accB.w *= r;
    split_store4(accA, g_m2h, g_m2l, w * HID + cA);
    split_store4(accB, g_m2h, g_m2l, w * HID + cB);
}

// ---------------- split-bf16 tensor-core GEMM ---------------------------------
// C = relu(A1@W1.T + A2@W2.T + bias), split bf16 hi/lo, 3-product scheme.
// Block 128x128, 128 threads (4 warps, 2x2), warp tile 64x64 (4x4 wmma frags).
// cp.async double-buffered tiles.

template <int K, bool BF16OUT>
__global__ __launch_bounds__(128) void gemmw_kernel(
    const __nv_bfloat16* __restrict__ A1h, const __nv_bfloat16* __restrict__ A1l,
    const __nv_bfloat16* __restrict__ W1h, const __nv_bfloat16* __restrict__ W1l,
    const __nv_bfloat16* __restrict__ A2h, const __nv_bfloat16* __restrict__ A2l,
    const __nv_bfloat16* __restrict__ W2h, const __nv_bfloat16* __restrict__ W2l,
    const float* __restrict__ bias,
    float* __restrict__ outF, __nv_bfloat16* __restrict__ outH,
    __nv_bfloat16* __restrict__ outL)
{
    const int BK = 32, LD = 40;
    const int S = 2 * K / BK;
    const int TILE = 128 * LD * 2;            // 10240 B per operand tile
    extern __shared__ char smraw[];
    // buffer b at smraw + b*4*TILE; order: Ah, Al, Bh, Bl
    float (*Cst)[132] = (float(*)[132])smraw;

    int t = threadIdx.x;                       // 128 threads
    int wid = t >> 5;
    int warpM = wid >> 1, warpN = wid & 1;     // 2x2 warps of 64x64
    int rowBase = blockIdx.x * 128, colBase = blockIdx.y * 128;

    wmma::fragment<wmma::accumulator, 16, 16, 16, float> acc[4][4];
#pragma unroll
    for (int i = 0; i < 4; i++)
#pragma unroll
        for (int j = 0; j < 4; j++) wmma::fill_fragment(acc[i][j], 0.f);

    // thread t loads row t (32 bf16 = 4 x 16B) of each of the 4 operand tiles
    auto issue = [&](int s) {
        int pass = (s * BK) / K;
        int k0 = (s * BK) % K;
        int b = s & 1;
        const __nv_bfloat16* pAh = (pass ? A2h : A1h) + (size_t)(rowBase + t) * K + k0;
        const __nv_bfloat16* pAl = (pass ? A2l : A1l) + (size_t)(rowBase + t) * K + k0;
        const __nv_bfloat16* pWh = (pass ? W2h : W1h) + (size_t)(colBase + t) * K + k0;
        const __nv_bfloat16* pWl = (pass ? W2l : W1l) + (size_t)(colBase + t) * K + k0;
        unsigned base = (unsigned)__cvta_generic_to_shared(smraw) + b * 4 * TILE + t * (LD * 2);
#pragma unroll
        for (int q = 0; q < 4; q++) {
            cpa16(base + 0 * TILE + q * 16, pAh + q * 8);
            cpa16(base + 1 * TILE + q * 16, pAl + q * 8);
            cpa16(base + 2 * TILE + q * 16, pWh + q * 8);
            cpa16(base + 3 * TILE + q * 16, pWl + q * 8);
        }
        cpa_commit();
    };

    auto compute = [&](int b) {
        const __nv_bfloat16* Ah = (const __nv_bfloat16*)(smraw + b * 4 * TILE);
        const __nv_bfloat16* Al = Ah + 128 * LD;
        const __nv_bfloat16* Bh = Al + 128 * LD;
        const __nv_bfloat16* Bl = Bh + 128 * LD;
#pragma unroll
        for (int kk = 0; kk < BK; kk += 16) {
            wmma::fragment<wmma::matrix_b, 16, 16, 16, __nv_bfloat16, wmma::col_major> bh[4], bl[4];
#pragma unroll
            for (int j = 0; j < 4; j++) {
                wmma::load_matrix_sync(bh[j], &Bh[(warpN * 64 + j * 16) * LD + kk], LD);
                wmma::load_matrix_sync(bl[j], &Bl[(warpN * 64 + j * 16) * LD + kk], LD);
            }
#pragma unroll
            for (int i = 0; i < 4; i++) {
                wmma::fragment<wmma::matrix_a, 16, 16, 16, __nv_bfloat16, wmma::row_major> ah, al;
                wmma::load_matrix_sync(ah, &Ah[(warpM * 64 + i * 16) * LD + kk], LD);
                wmma::load_matrix_sync(al, &Al[(warpM * 64 + i * 16) * LD + kk], LD);
#pragma unroll
                for (int j = 0; j < 4; j++) {
                    wmma::mma_sync(acc[i][j], ah, bh[j], acc[i][j]);
                    wmma::mma_sync(acc[i][j], ah, bl[j], acc[i][j]);
                    wmma::mma_sync(acc[i][j], al, bh[j], acc[i][j]);
                }
            }
        }
    };

    issue(0);
    for (int s = 0; s < S; s++) {
        if (s + 1 < S) {
            issue(s + 1);
            cpa_wait<1>();
        } else {
            cpa_wait<0>();
        }
        __syncthreads();
        compute(s & 1);
        __syncthreads();
    }

    // epilogue: stage fp32 in smem (buffers dead), then bias+relu+store
#pragma unroll
    for (int i = 0; i < 4; i++)
#pragma unroll
        for (int j = 0; j < 4; j++)
            wmma::store_matrix_sync(&Cst[warpM * 64 + i * 16][warpN * 64 + j * 16],
                                    acc[i][j], 132, wmma::mem_row_major);
    __syncthreads();

    size_t row = rowBase + t;
#pragma unroll
    for (int c = 0; c < 128; c += 4) {
        float4 v = *(float4*)&Cst[t][c];
        float4 bi = *(const float4*)&bias[colBase + c];
        float4 o;
        o.x = fmaxf(v.x + bi.x, 0.f);
        o.y = fmaxf(v.y + bi.y, 0.f);
        o.z = fmaxf(v.z + bi.z, 0.f);
        o.w = fmaxf(v.w + bi.w, 0.f);
        if (BF16OUT) {
            split_store4(o, outH, outL, (int)(row * HID + colBase + c));
        } else {
            *(float4*)&outF[row * HID + colBase + c] = o;
        }
    }
}

// ---------------- final-layer algebra ----------------------------------------

__global__ void vprep_kernel(const float* __restrict__ w_out,
                             const float* __restrict__ b_out,
                             const float* __restrict__ w_edge) {
    int k = threadIdx.x;  // 256 threads
    float sl = 0.f, sr = 0.f;
    for (int o = 0; o < HID; o++) {
        float w = w_out[o * HID + k];
        sl += w * w_edge[o];
        sr += w * w_edge[HID + o];
    }
    g_vl[k] = sl;
    g_vr[k] = sr;
    if (k == 0) {
        float cl = 0.f, cr = 0.f;
        for (int o = 0; o < HID; o++) {
            cl += b_out[o] * w_edge[o];
            cr += b_out[o] * w_edge[HID + o];
        }
        g_cc[0] = cl;
        g_cc[1] = cr;
    }
}

__global__ void lilj_kernel(const float* __restrict__ h) {
    int w = (blockIdx.x * blockDim.x + threadIdx.x) >> 5;
    if (w >= NN) return;
    int lane = threadIdx.x & 31;
    int k = lane * 8;
    float4 p0 = *(const float4*)&h[(size_t)w * HID + k];
    float4 p1 = *(const float4*)&h[(size_t)w * HID + k + 4];
    float4 vl0 = *(const float4*)&g_vl[k];
    float4 vl1 = *(const float4*)&g_vl[k + 4];
    float4 vr0 = *(const float4*)&g_vr[k];
    float4 vr1 = *(const float4*)&g_vr[k + 4];
    float sl = p0.x * vl0.x + p0.y * vl0.y + p0.z * vl0.z + p0.w * vl0.w +
               p1.x * vl1.x + p1.y * vl1.y + p1.z * vl1.z + p1.w * vl1.w;
    float sr = p0.x * vr0.x + p0.y * vr0.y + p0.z * vr0.z + p0.w * vr0.w +
               p1.x * vr1.x + p1.y * vr1.y + p1.z * vr1.z + p1.w * vr1.w;
#pragma unroll
    for (int off = 16; off > 0; off >>= 1) {
        sl += __shfl_xor_sync(0xFFFFFFFFu, sl, off);
        sr += __shfl_xor_sync(0xFFFFFFFFu, sr, off);
    }
    if (lane == 0) {
        g_li[w] = sl + g_cc[0];
        g_lj[w] = sr + g_cc[1];
    }
}

// ---------------- rank-1 broadcast output ------------------------------------

__global__ __launch_bounds__(256) void out_kernel(float* __restrict__ out,
                                                  const float* __restrict__ b_edge) {
    __shared__ float slj[2048];
    __shared__ float sli[16];
    int colBase = blockIdx.x * 2048;
    int rowBase = blockIdx.y * 16;
    float be = b_edge[0];
    for (int c = threadIdx.x; c < 2048; c += 256) slj[c] = g_lj[colBase + c];
    if (threadIdx.x < 16) sli[threadIdx.x] = g_li[rowBase + threadIdx.x];
    __syncthreads();
#pragma unroll 4
    for (int r = 0; r < 16; r++) {
        float liv = sli[r] + be;
        size_t base = (size_t)(rowBase + r) * NN + colBase;
        for (int c = threadIdx.x; c < 512; c += 256) {
            float4 v = *(const float4*)&slj[c * 4];
            float4 o = make_float4(liv + v.x, liv + v.y, liv + v.z, liv + v.w);
            __stcs((float4*)&out[base + c * 4], o);
        }
    }
}

// ---------------- launcher ----------------------------------------------------

extern "C" void kernel_launch(void* const* d_in, const int* in_sizes, int n_in,
                              void* d_out, int out_size) {
    const float* x      = (const float*)d_in[0];
    const int*   edges  = (const int*)d_in[1];   // probed: int64 or int32
    const float* wl1    = (const float*)d_in[2];
    const float* bl1    = (const float*)d_in[3];
    const float* wr1    = (const float*)d_in[4];
    const float* wl2    = (const float*)d_in[5];
    const float* bl2    = (const float*)d_in[6];
    const float* wr2    = (const float*)d_in[7];
    const float* w_out  = (const float*)d_in[8];
    const float* b_out  = (const float*)d_in[9];
    const float* w_edge = (const float*)d_in[10];
    const float* b_edge = (const float*)d_in[11];
    float* out = (float*)d_out;

    int n_edges = NE;
    const int GEMM_SMEM = 2 * 4 * 128 * 40 * 2;   // 81920 bytes (2 buffers x 4 tiles)

    static bool attr_set = false;
    if (!attr_set) {
        cudaFuncSetAttribute(gemmw_kernel<IND, true>,
                             cudaFuncAttributeMaxDynamicSharedMemorySize, GEMM_SMEM);
        cudaFuncSetAttribute(gemmw_kernel<HID, false>,
                             cudaFuncAttributeMaxDynamicSharedMemorySize, GEMM_SMEM);
        attr_set = true;
    }

    __nv_bfloat16 *xh, *xl, *m1h, *m1l, *h1h, *h1l, *m2h, *m2l;
    __nv_bfloat16 *wl1h, *wl1l, *wr1h, *wr1l, *wl2h, *wl2l, *wr2h, *wr2l;
    float* h2;
    cudaGetSymbolAddress((void**)&xh, g_xh);   cudaGetSymbolAddress((void**)&xl, g_xl);
    cudaGetSymbolAddress((void**)&m1h, g_m1h); cudaGetSymbolAddress((void**)&m1l, g_m1l);
    cudaGetSymbolAddress((void**)&h1h, g_h1h); cudaGetSymbolAddress((void**)&h1l, g_h1l);
    cudaGetSymbolAddress((void**)&m2h, g_m2h); cudaGetSymbolAddress((void**)&m2l, g_m2l);
    cudaGetSymbolAddress((void**)&wl1h, g_wl1h); cudaGetSymbolAddress((void**)&wl1l, g_wl1l);
    cudaGetSymbolAddress((void**)&wr1h, g_wr1h); cudaGetSymbolAddress((void**)&wr1l, g_wr1l);
    cudaGetSymbolAddress((void**)&wl2h, g_wl2h); cudaGetSymbolAddress((void**)&wl2l, g_wl2l);
    cudaGetSymbolAddress((void**)&wr2h, g_wr2h); cudaGetSymbolAddress((void**)&wr2l, g_wr2l);
    cudaGetSymbolAddress((void**)&h2, g_h2);

    // prep: degi zero (32) + probe (1) + weight cvt (192) + x cvt (1024)
    prep_kernel<<<1249, 256>>>(edges, x, wl1, wr1, wl2, wr2);
    convert_kernel<<<NE / 512, 256>>>(edges, n_edges);
    scan_kernel<<<1, 1024>>>();
    fill_kernel<<<NE / 512, 256>>>(n_edges);

    // layer 1
    agg128_kernel<<<NN * 32 / 256, 256>>>(x);
    {
        dim3 grid(NN / 128, HID / 128);
        gemmw_kernel<IND, true><<<grid, 128, GEMM_SMEM>>>(
            m1h, m1l, wl1h, wl1l, xh, xl, wr1h, wr1l, bl1, nullptr, h1h, h1l);
    }
    // layer 2
    agg256_kernel<<<NN * 32 / 256, 256>>>();
    {
        dim3 grid(NN / 128, HID / 128);
        gemmw_kernel<HID, false><<<grid, 128, GEMM_SMEM>>>(
            m2h, m2l, wl2h, wl2l, h1h, h1l, wr2h, wr2l, bl2, h2, nullptr, nullptr);
    }
    // output head
    vprep_kernel<<<1, 256>>>(w_out, b_out, w_edge);
    lilj_kernel<<<NN * 32 / 256, 256>>>(h2);
    {
        dim3 grid(NN / 2048, NN / 16);
        out_kernel<<<grid, 256>>>(out, b_edge);
    }
}